// round 2
// baseline (speedup 1.0000x reference)
#include <cuda_runtime.h>
#include <cstdint>

#define Bb   256
#define Tt   64
#define OBSn 4096
#define Dd   1024
#define Aa   8
#define Hh   2048
#define ZLn  4
#define ZDn  256
#define BT   (Bb*Tt)          // 16384
#define EPSf 1e-5f

// ---------------- scratch (static device globals; no allocation) -------------
__device__ float g_h1[BT * Hh];        // encoder hidden   [16384,2048]
__device__ float g_x [BT * Dd];        // encoder out      [16384,1024]
__device__ float g_gi[BT * 3 * Dd];    // gi = x@wih^T+bih [16384,3072]
__device__ float g_hj[Bb * Dd];
__device__ float g_gh[Bb * 3 * Dd];
__device__ float g_h [Bb * Dd];
__device__ float g_z [Bb * ZLn * ZDn];
__device__ float g_d1[Bb * Hh];
__device__ float g_d2[Bb * OBSn];
__device__ float g_mean[4096];
__device__ float g_var [4096];

// ---------------- SGEMM: C = A @ B^T + bias ----------------------------------
// A: M x K (row-major, stride lda); B: N x K (row-major, stride ldb);
// C: M x N (row-major, stride ldc).  Requires M%128==0, N%128==0, K%8==0.
#define BM 128
#define BN 128
#define BK 8

__global__ void __launch_bounds__(256)
sgemm_abt(const float* __restrict__ A, const float* __restrict__ Bm,
          const float* __restrict__ bias, float* __restrict__ C,
          int M, int N, int K, int lda, int ldb, int ldc)
{
    __shared__ float As[BK][BM];
    __shared__ float Bs[BK][BN];

    const int tid = threadIdx.x;
    const int tx = tid & 15;        // 0..15 -> col group
    const int ty = tid >> 4;        // 0..15 -> row group
    const int rowBase = blockIdx.y * BM;
    const int colBase = blockIdx.x * BN;

    const int lr = tid >> 1;        // 0..127 (tile row)
    const int lc = (tid & 1) * 4;   // 0 or 4 (k offset)

    const float* Aptr = A + (size_t)(rowBase + lr) * lda + lc;
    const float* Bptr = Bm + (size_t)(colBase + lr) * ldb + lc;

    float acc[8][8];
#pragma unroll
    for (int i = 0; i < 8; i++)
#pragma unroll
        for (int j = 0; j < 8; j++) acc[i][j] = 0.f;

    for (int k0 = 0; k0 < K; k0 += BK) {
        float4 av = *(const float4*)(Aptr + k0);
        float4 bv = *(const float4*)(Bptr + k0);
        As[lc + 0][lr] = av.x; As[lc + 1][lr] = av.y;
        As[lc + 2][lr] = av.z; As[lc + 3][lr] = av.w;
        Bs[lc + 0][lr] = bv.x; Bs[lc + 1][lr] = bv.y;
        Bs[lc + 2][lr] = bv.z; Bs[lc + 3][lr] = bv.w;
        __syncthreads();
#pragma unroll
        for (int kk = 0; kk < BK; kk++) {
            float a[8], b[8];
#pragma unroll
            for (int i = 0; i < 8; i++) a[i] = As[kk][ty * 8 + i];
#pragma unroll
            for (int j = 0; j < 8; j++) b[j] = Bs[kk][tx * 8 + j];
#pragma unroll
            for (int i = 0; i < 8; i++)
#pragma unroll
                for (int j = 0; j < 8; j++)
                    acc[i][j] = fmaf(a[i], b[j], acc[i][j]);
        }
        __syncthreads();
    }

#pragma unroll
    for (int i = 0; i < 8; i++) {
        const int r = rowBase + ty * 8 + i;
#pragma unroll
        for (int j = 0; j < 8; j++) {
            const int c = colBase + tx * 8 + j;
            C[(size_t)r * ldc + c] = acc[i][j] + bias[c];
        }
    }
}

// ---------------- per-column batch statistics (biased var) -------------------
__global__ void col_stats(const float* __restrict__ X, int M, int N,
                          float* __restrict__ mean, float* __restrict__ var)
{
    const int c = blockIdx.x * 32 + threadIdx.x;
    const int ry = threadIdx.y;
    float s = 0.f, s2 = 0.f;
    for (int r = ry; r < M; r += 8) {
        float v = X[(size_t)r * N + c];
        s += v; s2 += v * v;
    }
    __shared__ float sh[8][32], sh2[8][32];
    sh[ry][threadIdx.x] = s; sh2[ry][threadIdx.x] = s2;
    __syncthreads();
    if (ry == 0) {
#pragma unroll
        for (int y = 1; y < 8; y++) { s += sh[y][threadIdx.x]; s2 += sh2[y][threadIdx.x]; }
        float m = s / (float)M;
        mean[c] = m;
        var[c]  = s2 / (float)M - m * m;
    }
}

// ---------------- BN apply (+ optional ReLU) ---------------------------------
__global__ void bn_apply(const float* __restrict__ X, float* __restrict__ Y,
                         const float* __restrict__ mean, const float* __restrict__ var,
                         const float* __restrict__ g, const float* __restrict__ beta,
                         int total, int N, int relu)
{
    int idx = blockIdx.x * blockDim.x + threadIdx.x;
    if (idx >= total) return;
    int c = idx % N;
    float v = g[c] * (X[idx] - mean[c]) * rsqrtf(var[c] + EPSf) + beta[c];
    if (relu) v = fmaxf(v, 0.f);
    Y[idx] = v;
}

// ---------------- scan helpers ----------------------------------------------
__global__ void zero_h() {
    int idx = blockIdx.x * blockDim.x + threadIdx.x;
    if (idx < Bb * Dd) g_h[idx] = 0.f;
}

// hj += actions[:,t,:] @ je_w[:, D:D+A]^T   (the K=8 tail of the concat GEMM)
__global__ void add_action(const float* __restrict__ actions,
                           const float* __restrict__ je_w, int t)
{
    int idx = blockIdx.x * blockDim.x + threadIdx.x;   // B*D
    if (idx >= Bb * Dd) return;
    int b = idx >> 10;            // /1024
    int d = idx & 1023;
    const float* a = actions + ((size_t)(b * Tt + t)) * Aa;
    const float* w = je_w + (size_t)d * (Dd + Aa) + Dd;
    float s = 0.f;
#pragma unroll
    for (int j = 0; j < Aa; j++) s = fmaf(a[j], w[j], s);
    g_hj[idx] += s;
}

__device__ __forceinline__ float sigmoidf_(float x) { return 1.f / (1.f + expf(-x)); }

// h_new = (1-z)*n + z*hj + x_t
__global__ void gru_gate(int t)
{
    int idx = blockIdx.x * blockDim.x + threadIdx.x;   // B*D
    if (idx >= Bb * Dd) return;
    int b = idx >> 10;
    int d = idx & 1023;
    int row = b * Tt + t;
    const float* gi = g_gi + (size_t)row * (3 * Dd);
    const float* gh = g_gh + (size_t)b * (3 * Dd);
    float ir = gi[d], iz = gi[Dd + d], in_ = gi[2 * Dd + d];
    float hr = gh[d], hz = gh[Dd + d], hn = gh[2 * Dd + d];
    float r = sigmoidf_(ir + hr);
    float z = sigmoidf_(iz + hz);
    float n = tanhf(in_ + r * hn);
    float hjv = g_hj[idx];
    float xv = g_x[(size_t)row * Dd + d];
    g_h[idx] = (1.f - z) * n + z * hjv + xv;
}

// ---------------- threefry2x32-20 (JAX-exact) --------------------------------
__device__ __forceinline__ uint32_t rotl32_(uint32_t x, int r) {
    return (x << r) | (x >> (32 - r));
}

__device__ __forceinline__ void threefry2x32_(uint32_t k0, uint32_t k1,
                                              uint32_t& x0, uint32_t& x1)
{
    const uint32_t k2 = k0 ^ k1 ^ 0x1BD11BDAu;
    x0 += k0; x1 += k1;
#define TF_R4(a,b,c,d) \
    x0 += x1; x1 = rotl32_(x1, a); x1 ^= x0; \
    x0 += x1; x1 = rotl32_(x1, b); x1 ^= x0; \
    x0 += x1; x1 = rotl32_(x1, c); x1 ^= x0; \
    x0 += x1; x1 = rotl32_(x1, d); x1 ^= x0;
    TF_R4(13,15,26,6)  x0 += k1; x1 += k2 + 1u;
    TF_R4(17,29,16,24) x0 += k2; x1 += k0 + 2u;
    TF_R4(13,15,26,6)  x0 += k0; x1 += k1 + 3u;
    TF_R4(17,29,16,24) x0 += k1; x1 += k2 + 4u;
    TF_R4(13,15,26,6)  x0 += k2; x1 += k0 + 5u;
#undef TF_R4
}

// gumbel-softmax over last dim (ZD=256). One block per (b, zl) row.
// Emits logits to out[0:BZ], z to out[BZ:2BZ] and g_z.
// RNG: JAX partitionable threefry (default since jax 0.4.30):
//   per element i: counter64 = i -> (hi, lo) = (0, i);
//   (o0, o1) = threefry2x32(key=(0,42), (hi, lo)); bits = o0 ^ o1.
__global__ void gumbel_softmax_k(float* __restrict__ out)
{
    const int bl = blockIdx.x;          // 0..1023 = b*ZL + l
    const int d  = threadIdx.x;         // 0..255
    const int i  = bl * ZDn + d;        // flat index into (B,ZL,ZD) == g_h layout
    const float logit = g_h[i];

    uint32_t c0 = 0u;                   // hi32 of 64-bit counter (n < 2^32)
    uint32_t c1 = (uint32_t)i;          // lo32
    threefry2x32_(0u, 42u, c0, c1);
    const uint32_t bits = c0 ^ c1;
    float f = __uint_as_float((bits >> 9) | 0x3f800000u) - 1.0f;   // [0,1)
    const float tiny = 1.1754943508222875e-38f;
    float u = fmaxf(f * (1.0f - tiny) + tiny, tiny);
    float gum = -logf(-logf(u));

    float v = logit + gum;              // TAU = 1.0

    __shared__ float red[ZDn];
    red[d] = v; __syncthreads();
    for (int s = ZDn / 2; s > 0; s >>= 1) {
        if (d < s) red[d] = fmaxf(red[d], red[d + s]);
        __syncthreads();
    }
    float mx = red[0];
    __syncthreads();
    float e = expf(v - mx);
    red[d] = e; __syncthreads();
    for (int s = ZDn / 2; s > 0; s >>= 1) {
        if (d < s) red[d] += red[d + s];
        __syncthreads();
    }
    float z = e / red[0];

    out[i] = logit;                       // logits
    out[Bb * ZLn * ZDn + i] = z;          // z
    g_z[i] = z;                           // decoder input
}

// ---------------- launch ------------------------------------------------------
static inline float* sym(const void* s) {
    void* p = nullptr;
    cudaGetSymbolAddress(&p, s);
    return (float*)p;
}

extern "C" void kernel_launch(void* const* d_in, const int* in_sizes, int n_in,
                              void* d_out, int out_size)
{
    (void)in_sizes; (void)n_in; (void)out_size;
    const float* obs      = (const float*)d_in[0];
    const float* actions  = (const float*)d_in[1];
    const float* enc_w1   = (const float*)d_in[2];
    const float* enc_b1   = (const float*)d_in[3];
    const float* enc_g1   = (const float*)d_in[4];
    const float* enc_bt1  = (const float*)d_in[5];
    const float* enc_w2   = (const float*)d_in[6];
    const float* enc_b2   = (const float*)d_in[7];
    const float* enc_g2   = (const float*)d_in[8];
    const float* enc_bt2  = (const float*)d_in[9];
    const float* je_w     = (const float*)d_in[10];
    const float* je_b     = (const float*)d_in[11];
    const float* gru_wih  = (const float*)d_in[12];
    const float* gru_bih  = (const float*)d_in[13];
    const float* gru_whh  = (const float*)d_in[14];
    const float* gru_bhh  = (const float*)d_in[15];
    const float* dec_w1   = (const float*)d_in[16];
    const float* dec_b1   = (const float*)d_in[17];
    const float* dec_g1   = (const float*)d_in[18];
    const float* dec_bt1  = (const float*)d_in[19];
    const float* dec_w2   = (const float*)d_in[20];
    const float* dec_b2   = (const float*)d_in[21];
    const float* dec_g2   = (const float*)d_in[22];
    const float* dec_bt2  = (const float*)d_in[23];
    float* out = (float*)d_out;

    float* p_h1 = sym(g_h1);
    float* p_x  = sym(g_x);
    float* p_gi = sym(g_gi);
    float* p_hj = sym(g_hj);
    float* p_gh = sym(g_gh);
    float* p_h  = sym(g_h);
    float* p_z  = sym(g_z);
    float* p_d1 = sym(g_d1);
    float* p_d2 = sym(g_d2);
    float* p_m  = sym(g_mean);
    float* p_v  = sym(g_var);

    dim3 blk(256);
    dim3 statsBlk(32, 8);

    // ---- encoder layer 1: h1 = relu(BN(obs@W1^T+b1)) ----
    {
        dim3 grid(Hh / BN, BT / BM);
        sgemm_abt<<<grid, blk>>>(obs, enc_w1, enc_b1, p_h1, BT, Hh, OBSn, OBSn, OBSn, Hh);
        col_stats<<<Hh / 32, statsBlk>>>(p_h1, BT, Hh, p_m, p_v);
        int total = BT * Hh;
        bn_apply<<<(total + 255) / 256, blk>>>(p_h1, p_h1, p_m, p_v, enc_g1, enc_bt1, total, Hh, 1);
    }
    // ---- encoder layer 2: x = BN(h1@W2^T+b2) ----
    {
        dim3 grid(Dd / BN, BT / BM);
        sgemm_abt<<<grid, blk>>>(p_h1, enc_w2, enc_b2, p_x, BT, Dd, Hh, Hh, Hh, Dd);
        col_stats<<<Dd / 32, statsBlk>>>(p_x, BT, Dd, p_m, p_v);
        int total = BT * Dd;
        bn_apply<<<(total + 255) / 256, blk>>>(p_x, p_x, p_m, p_v, enc_g2, enc_bt2, total, Dd, 0);
    }
    // ---- gi = x @ wih^T + bih (all timesteps at once) ----
    {
        dim3 grid(3 * Dd / BN, BT / BM);
        sgemm_abt<<<grid, blk>>>(p_x, gru_wih, gru_bih, p_gi, BT, 3 * Dd, Dd, Dd, Dd, 3 * Dd);
    }
    // ---- recurrent scan ----
    zero_h<<<(Bb * Dd + 255) / 256, blk>>>();
    for (int t = 0; t < Tt; t++) {
        // hj = h @ je_w[:, :D]^T + je_b
        dim3 gridHj(Dd / BN, Bb / BM);
        sgemm_abt<<<gridHj, blk>>>(p_h, je_w, je_b, p_hj, Bb, Dd, Dd, Dd, Dd + Aa, Dd);
        add_action<<<(Bb * Dd + 255) / 256, blk>>>(actions, je_w, t);
        // gh = hj @ whh^T + bhh
        dim3 gridGh(3 * Dd / BN, Bb / BM);
        sgemm_abt<<<gridGh, blk>>>(p_hj, gru_whh, gru_bhh, p_gh, Bb, 3 * Dd, Dd, Dd, Dd, 3 * Dd);
        gru_gate<<<(Bb * Dd + 255) / 256, blk>>>(t);
    }
    // ---- gumbel softmax: logits -> out[0:], z -> out[BZ:], g_z ----
    gumbel_softmax_k<<<Bb * ZLn, ZDn>>>(out);
    // ---- decoder layer 1 ----
    {
        dim3 grid(Hh / BN, Bb / BM);
        sgemm_abt<<<grid, blk>>>(p_z, dec_w1, dec_b1, p_d1, Bb, Hh, Dd, Dd, Dd, Hh);
        col_stats<<<Hh / 32, statsBlk>>>(p_d1, Bb, Hh, p_m, p_v);
        int total = Bb * Hh;
        bn_apply<<<(total + 255) / 256, blk>>>(p_d1, p_d1, p_m, p_v, dec_g1, dec_bt1, total, Hh, 1);
    }
    // ---- decoder layer 2 -> x_hat at out[2*BZ:] ----
    {
        dim3 grid(OBSn / BN, Bb / BM);
        sgemm_abt<<<grid, blk>>>(p_d1, dec_w2, dec_b2, p_d2, Bb, OBSn, Hh, Hh, Hh, OBSn);
        col_stats<<<OBSn / 32, statsBlk>>>(p_d2, Bb, OBSn, p_m, p_v);
        int total = Bb * OBSn;
        bn_apply<<<(total + 255) / 256, blk>>>(p_d2, out + 2 * Bb * ZLn * ZDn,
                                               p_m, p_v, dec_g2, dec_bt2, total, OBSn, 0);
    }
}

// round 3
// speedup vs baseline: 1.7450x; 1.7450x over previous
#include <cuda_runtime.h>
#include <cstdint>

#define Bb   256
#define Tt   64
#define OBSn 4096
#define Dd   1024
#define Aa   8
#define Hh   2048
#define ZLn  4
#define ZDn  256
#define BT   (Bb*Tt)          // 16384
#define EPSf 1e-5f
#define JEW_LD (Dd + Aa)      // 1032

// ---------------- scratch (static device globals; no allocation) -------------
__device__ float g_h1[BT * Hh];        // encoder hidden   [16384,2048]
__device__ float g_x [BT * Dd];        // encoder out      [16384,1024]
__device__ float g_gi[BT * 3 * Dd];    // gi = x@wih^T+bih [16384,3072]
__device__ float g_G [Bb * 4 * Dd];    // scan GEMM out    [256,4096]
__device__ float g_h [Bb * Dd];
__device__ float g_z [Bb * ZLn * ZDn];
__device__ float g_d1[Bb * Hh];
__device__ float g_d2[Bb * OBSn];
__device__ float g_mean[4096];
__device__ float g_var [4096];
__device__ float g_wscan[4 * Dd * Dd]; // [4096,1024]: rows 0-3071 = whh@jeW, 3072-4095 = jeW
__device__ float g_M2[3 * Dd * Aa];    // whh @ jeA  [3072,8]
__device__ float g_c [3 * Dd];         // whh @ je_b + bhh

// =============== double-buffered SGEMM: C = A @ B^T (+bias) ==================
// A: M x K (row-major, lda); B: N x K (row-major, ldb); C: M x N (ldc).
// BN fixed 128, TN fixed 8, 256 threads. BMv in {128, 64}; TMv = BMv/16.
#define BKd 8

template<int BMv, int TMv>
__global__ void __launch_bounds__(256)
sgemm_abt(const float* __restrict__ A, const float* __restrict__ Bm,
          const float* __restrict__ bias, float* __restrict__ C,
          int M, int N, int K, int lda, int ldb, int ldc)
{
    __shared__ float As[2][BKd][BMv];
    __shared__ float Bs[2][BKd][128];

    const int tid = threadIdx.x;
    const int tx = tid & 15;
    const int ty = tid >> 4;
    const int rowBase = blockIdx.y * BMv;
    const int colBase = blockIdx.x * 128;

    // load mapping
    const int lrB = tid >> 1;              // 0..127
    const int lcB = (tid & 1) * 4;
    const bool loadA = (BMv == 128) ? true : (tid < 128);
    const int lrA = (BMv == 128) ? (tid >> 1) : (tid >> 1); // 0..127 or 0..63 (tid<128)
    const int lcA = (tid & 1) * 4;

    const float* Aptr = A + (size_t)(rowBase + lrA) * lda + lcA;
    const float* Bptr = Bm + (size_t)(colBase + lrB) * ldb + lcB;

    float acc[TMv][8];
#pragma unroll
    for (int i = 0; i < TMv; i++)
#pragma unroll
        for (int j = 0; j < 8; j++) acc[i][j] = 0.f;

    // prologue: tile 0
    {
        float4 bv = *(const float4*)(Bptr);
        Bs[0][lcB + 0][lrB] = bv.x; Bs[0][lcB + 1][lrB] = bv.y;
        Bs[0][lcB + 2][lrB] = bv.z; Bs[0][lcB + 3][lrB] = bv.w;
        if (loadA) {
            float4 av = *(const float4*)(Aptr);
            As[0][lcA + 0][lrA] = av.x; As[0][lcA + 1][lrA] = av.y;
            As[0][lcA + 2][lrA] = av.z; As[0][lcA + 3][lrA] = av.w;
        }
    }
    __syncthreads();

    int buf = 0;
    for (int k0 = 0; k0 < K; k0 += BKd) {
        const bool more = (k0 + BKd) < K;
        float4 av2, bv2;
        if (more) {
            bv2 = *(const float4*)(Bptr + k0 + BKd);
            if (loadA) av2 = *(const float4*)(Aptr + k0 + BKd);
        }
#pragma unroll
        for (int kk = 0; kk < BKd; kk++) {
            float a[TMv], b[8];
#pragma unroll
            for (int i = 0; i < TMv; i++) a[i] = As[buf][kk][ty * TMv + i];
#pragma unroll
            for (int j = 0; j < 8; j++) b[j] = Bs[buf][kk][tx * 8 + j];
#pragma unroll
            for (int i = 0; i < TMv; i++)
#pragma unroll
                for (int j = 0; j < 8; j++)
                    acc[i][j] = fmaf(a[i], b[j], acc[i][j]);
        }
        if (more) {
            const int nb = buf ^ 1;
            Bs[nb][lcB + 0][lrB] = bv2.x; Bs[nb][lcB + 1][lrB] = bv2.y;
            Bs[nb][lcB + 2][lrB] = bv2.z; Bs[nb][lcB + 3][lrB] = bv2.w;
            if (loadA) {
                As[nb][lcA + 0][lrA] = av2.x; As[nb][lcA + 1][lrA] = av2.y;
                As[nb][lcA + 2][lrA] = av2.z; As[nb][lcA + 3][lrA] = av2.w;
            }
            __syncthreads();
            buf = nb;
        }
    }

#pragma unroll
    for (int i = 0; i < TMv; i++) {
        const int r = rowBase + ty * TMv + i;
#pragma unroll
        for (int j = 0; j < 8; j++) {
            const int c = colBase + tx * 8 + j;
            float bv = bias ? bias[c] : 0.f;
            C[(size_t)r * ldc + c] = acc[i][j] + bv;
        }
    }
}

// =============== SGEMM (no transpose): C = A @ B =============================
// A: M x K (lda); B: K x N (ldb); C: M x N (ldc). 128x128 tile, single-buffer
// (only used for the small precompute M1 = whh @ jeW).
__global__ void __launch_bounds__(256)
sgemm_ab(const float* __restrict__ A, const float* __restrict__ Bm,
         float* __restrict__ C, int M, int N, int K, int lda, int ldb, int ldc)
{
    __shared__ float As[BKd][128];
    __shared__ float Bs[BKd][128];

    const int tid = threadIdx.x;
    const int tx = tid & 15;
    const int ty = tid >> 4;
    const int rowBase = blockIdx.y * 128;
    const int colBase = blockIdx.x * 128;

    const int lrA = tid >> 1;
    const int lcA = (tid & 1) * 4;
    const int kkB = tid >> 5;           // 0..7
    const int c4B = (tid & 31) * 4;     // 0..124

    const float* Aptr = A + (size_t)(rowBase + lrA) * lda + lcA;
    const float* Bptr = Bm + (size_t)kkB * ldb + colBase + c4B;

    float acc[8][8];
#pragma unroll
    for (int i = 0; i < 8; i++)
#pragma unroll
        for (int j = 0; j < 8; j++) acc[i][j] = 0.f;

    for (int k0 = 0; k0 < K; k0 += BKd) {
        float4 av = *(const float4*)(Aptr + k0);
        float4 bv = *(const float4*)(Bptr + (size_t)k0 * ldb);
        As[lcA + 0][lrA] = av.x; As[lcA + 1][lrA] = av.y;
        As[lcA + 2][lrA] = av.z; As[lcA + 3][lrA] = av.w;
        *(float4*)&Bs[kkB][c4B] = bv;
        __syncthreads();
#pragma unroll
        for (int kk = 0; kk < BKd; kk++) {
            float a[8], b[8];
#pragma unroll
            for (int i = 0; i < 8; i++) a[i] = As[kk][ty * 8 + i];
#pragma unroll
            for (int j = 0; j < 8; j++) b[j] = Bs[kk][tx * 8 + j];
#pragma unroll
            for (int i = 0; i < 8; i++)
#pragma unroll
                for (int j = 0; j < 8; j++)
                    acc[i][j] = fmaf(a[i], b[j], acc[i][j]);
        }
        __syncthreads();
    }
#pragma unroll
    for (int i = 0; i < 8; i++) {
        const int r = rowBase + ty * 8 + i;
#pragma unroll
        for (int j = 0; j < 8; j++)
            C[(size_t)r * ldc + colBase + tx * 8 + j] = acc[i][j];
    }
}

// copy jeW (rows of je_w, first D cols) into W_scan rows 3072..4095
__global__ void copy_jew(const float* __restrict__ je_w)
{
    int idx = blockIdx.x * blockDim.x + threadIdx.x;  // D*D
    if (idx >= Dd * Dd) return;
    int j = idx >> 10, k = idx & 1023;
    g_wscan[(size_t)(3 * Dd + j) * Dd + k] = je_w[(size_t)j * JEW_LD + k];
}

// M2[i][0:8] = sum_k whh[i][k]*je_w[k][1024+j];  c[i] = sum_k whh[i][k]*je_b[k] + bhh[i]
__global__ void __launch_bounds__(128)
m2c_k(const float* __restrict__ whh, const float* __restrict__ je_w,
      const float* __restrict__ je_b, const float* __restrict__ bhh)
{
    const int i = blockIdx.x;          // 0..3071
    const int t = threadIdx.x;         // 0..127
    float acc[9];
#pragma unroll
    for (int j = 0; j < 9; j++) acc[j] = 0.f;
    for (int k = t; k < Dd; k += 128) {
        float w = whh[(size_t)i * Dd + k];
        const float* jr = je_w + (size_t)k * JEW_LD + Dd;
#pragma unroll
        for (int j = 0; j < 8; j++) acc[j] = fmaf(w, jr[j], acc[j]);
        acc[8] = fmaf(w, je_b[k], acc[8]);
    }
    __shared__ float sh[9][128];
#pragma unroll
    for (int j = 0; j < 9; j++) sh[j][t] = acc[j];
    __syncthreads();
    for (int s = 64; s > 0; s >>= 1) {
        if (t < s)
#pragma unroll
            for (int j = 0; j < 9; j++) sh[j][t] += sh[j][t + s];
        __syncthreads();
    }
    if (t == 0) {
#pragma unroll
        for (int j = 0; j < 8; j++) g_M2[i * 8 + j] = sh[j][0];
        g_c[i] = sh[8][0] + bhh[i];
    }
}

// ---------------- per-column batch statistics (biased var) -------------------
__global__ void col_stats(const float* __restrict__ X, int M, int N,
                          float* __restrict__ mean, float* __restrict__ var)
{
    const int c = blockIdx.x * 32 + threadIdx.x;
    const int ry = threadIdx.y;
    float s = 0.f, s2 = 0.f;
    for (int r = ry; r < M; r += 8) {
        float v = X[(size_t)r * N + c];
        s += v; s2 += v * v;
    }
    __shared__ float sh[8][32], sh2[8][32];
    sh[ry][threadIdx.x] = s; sh2[ry][threadIdx.x] = s2;
    __syncthreads();
    if (ry == 0) {
#pragma unroll
        for (int y = 1; y < 8; y++) { s += sh[y][threadIdx.x]; s2 += sh2[y][threadIdx.x]; }
        float m = s / (float)M;
        mean[c] = m;
        var[c]  = s2 / (float)M - m * m;
    }
}

// ---------------- BN apply (+ optional ReLU) ---------------------------------
__global__ void bn_apply(const float* __restrict__ X, float* __restrict__ Y,
                         const float* __restrict__ mean, const float* __restrict__ var,
                         const float* __restrict__ g, const float* __restrict__ beta,
                         int total, int N, int relu)
{
    int idx = blockIdx.x * blockDim.x + threadIdx.x;
    if (idx >= total) return;
    int c = idx % N;
    float v = g[c] * (X[idx] - mean[c]) * rsqrtf(var[c] + EPSf) + beta[c];
    if (relu) v = fmaxf(v, 0.f);
    Y[idx] = v;
}

// ---------------- scan ------------------------------------------------------
__global__ void zero_h() {
    int idx = blockIdx.x * blockDim.x + threadIdx.x;
    if (idx < Bb * Dd) g_h[idx] = 0.f;
}

__device__ __forceinline__ float sigmoidf_(float x) { return 1.f / (1.f + expf(-x)); }

// Consumes G = h @ W_scan^T (cols 0-3071: gh core; 3072-4095: hj core),
// adds action terms + folded biases, applies GRU gates + residual.
__global__ void gru_gate2(const float* __restrict__ actions,
                          const float* __restrict__ je_w,
                          const float* __restrict__ je_b, int t)
{
    int idx = blockIdx.x * blockDim.x + threadIdx.x;   // B*D
    if (idx >= Bb * Dd) return;
    int b = idx >> 10;
    int d = idx & 1023;
    int row = b * Tt + t;

    const float* a = actions + (size_t)row * Aa;
    float av[8];
#pragma unroll
    for (int j = 0; j < 8; j++) av[j] = a[j];

    const float* G = g_G + (size_t)b * (4 * Dd);

    float hr = G[d]          + g_c[d];
    float hz = G[Dd + d]     + g_c[Dd + d];
    float hn = G[2 * Dd + d] + g_c[2 * Dd + d];
    float hj = G[3 * Dd + d] + je_b[d];
    const float* m2r = g_M2 + (size_t)d * 8;
    const float* m2z = g_M2 + (size_t)(Dd + d) * 8;
    const float* m2n = g_M2 + (size_t)(2 * Dd + d) * 8;
    const float* jea = je_w + (size_t)d * JEW_LD + Dd;
#pragma unroll
    for (int j = 0; j < 8; j++) {
        hr = fmaf(av[j], m2r[j], hr);
        hz = fmaf(av[j], m2z[j], hz);
        hn = fmaf(av[j], m2n[j], hn);
        hj = fmaf(av[j], jea[j], hj);
    }

    const float* gi = g_gi + (size_t)row * (3 * Dd);
    float r = sigmoidf_(gi[d] + hr);
    float z = sigmoidf_(gi[Dd + d] + hz);
    float n = tanhf(gi[2 * Dd + d] + r * hn);
    float xv = g_x[(size_t)row * Dd + d];
    g_h[idx] = (1.f - z) * n + z * hj + xv;
}

// ---------------- threefry2x32-20 (JAX partitionable) ------------------------
__device__ __forceinline__ uint32_t rotl32_(uint32_t x, int r) {
    return (x << r) | (x >> (32 - r));
}

__device__ __forceinline__ void threefry2x32_(uint32_t k0, uint32_t k1,
                                              uint32_t& x0, uint32_t& x1)
{
    const uint32_t k2 = k0 ^ k1 ^ 0x1BD11BDAu;
    x0 += k0; x1 += k1;
#define TF_R4(a,b,c,d) \
    x0 += x1; x1 = rotl32_(x1, a); x1 ^= x0; \
    x0 += x1; x1 = rotl32_(x1, b); x1 ^= x0; \
    x0 += x1; x1 = rotl32_(x1, c); x1 ^= x0; \
    x0 += x1; x1 = rotl32_(x1, d); x1 ^= x0;
    TF_R4(13,15,26,6)  x0 += k1; x1 += k2 + 1u;
    TF_R4(17,29,16,24) x0 += k2; x1 += k0 + 2u;
    TF_R4(13,15,26,6)  x0 += k0; x1 += k1 + 3u;
    TF_R4(17,29,16,24) x0 += k1; x1 += k2 + 4u;
    TF_R4(13,15,26,6)  x0 += k2; x1 += k0 + 5u;
#undef TF_R4
}

__global__ void gumbel_softmax_k(float* __restrict__ out)
{
    const int bl = blockIdx.x;          // b*ZL + l
    const int d  = threadIdx.x;         // 0..255
    const int i  = bl * ZDn + d;
    const float logit = g_h[i];

    uint32_t c0 = 0u;
    uint32_t c1 = (uint32_t)i;
    threefry2x32_(0u, 42u, c0, c1);
    const uint32_t bits = c0 ^ c1;
    float f = __uint_as_float((bits >> 9) | 0x3f800000u) - 1.0f;
    const float tiny = 1.1754943508222875e-38f;
    float u = fmaxf(f * (1.0f - tiny) + tiny, tiny);
    float gum = -logf(-logf(u));

    float v = logit + gum;

    __shared__ float red[ZDn];
    red[d] = v; __syncthreads();
    for (int s = ZDn / 2; s > 0; s >>= 1) {
        if (d < s) red[d] = fmaxf(red[d], red[d + s]);
        __syncthreads();
    }
    float mx = red[0];
    __syncthreads();
    float e = expf(v - mx);
    red[d] = e; __syncthreads();
    for (int s = ZDn / 2; s > 0; s >>= 1) {
        if (d < s) red[d] += red[d + s];
        __syncthreads();
    }
    float z = e / red[0];

    out[i] = logit;
    out[Bb * ZLn * ZDn + i] = z;
    g_z[i] = z;
}

// ---------------- launch ------------------------------------------------------
static inline float* sym(const void* s) {
    void* p = nullptr;
    cudaGetSymbolAddress(&p, s);
    return (float*)p;
}

extern "C" void kernel_launch(void* const* d_in, const int* in_sizes, int n_in,
                              void* d_out, int out_size)
{
    (void)in_sizes; (void)n_in; (void)out_size;
    const float* obs      = (const float*)d_in[0];
    const float* actions  = (const float*)d_in[1];
    const float* enc_w1   = (const float*)d_in[2];
    const float* enc_b1   = (const float*)d_in[3];
    const float* enc_g1   = (const float*)d_in[4];
    const float* enc_bt1  = (const float*)d_in[5];
    const float* enc_w2   = (const float*)d_in[6];
    const float* enc_b2   = (const float*)d_in[7];
    const float* enc_g2   = (const float*)d_in[8];
    const float* enc_bt2  = (const float*)d_in[9];
    const float* je_w     = (const float*)d_in[10];
    const float* je_b     = (const float*)d_in[11];
    const float* gru_wih  = (const float*)d_in[12];
    const float* gru_bih  = (const float*)d_in[13];
    const float* gru_whh  = (const float*)d_in[14];
    const float* gru_bhh  = (const float*)d_in[15];
    const float* dec_w1   = (const float*)d_in[16];
    const float* dec_b1   = (const float*)d_in[17];
    const float* dec_g1   = (const float*)d_in[18];
    const float* dec_bt1  = (const float*)d_in[19];
    const float* dec_w2   = (const float*)d_in[20];
    const float* dec_b2   = (const float*)d_in[21];
    const float* dec_g2   = (const float*)d_in[22];
    const float* dec_bt2  = (const float*)d_in[23];
    float* out = (float*)d_out;

    float* p_h1 = sym(g_h1);
    float* p_x  = sym(g_x);
    float* p_gi = sym(g_gi);
    float* p_G  = sym(g_G);
    float* p_h  = sym(g_h);
    float* p_z  = sym(g_z);
    float* p_d1 = sym(g_d1);
    float* p_d2 = sym(g_d2);
    float* p_m  = sym(g_mean);
    float* p_v  = sym(g_var);
    float* p_ws = sym(g_wscan);

    dim3 blk(256);
    dim3 statsBlk(32, 8);

    // ---- precompute scan operators: W_scan = [whh@jeW ; jeW], M2, c ----
    {
        dim3 grid(Dd / 128, 3 * Dd / 128);   // (8, 24)
        sgemm_ab<<<grid, blk>>>(gru_whh, je_w, p_ws, 3 * Dd, Dd, Dd, Dd, JEW_LD, Dd);
        copy_jew<<<(Dd * Dd + 255) / 256, blk>>>(je_w);
        m2c_k<<<3 * Dd, 128>>>(gru_whh, je_w, je_b, gru_bhh);
    }

    // ---- encoder layer 1: h1 = relu(BN(obs@W1^T+b1)) ----
    {
        dim3 grid(Hh / 128, BT / 128);
        sgemm_abt<128, 8><<<grid, blk>>>(obs, enc_w1, enc_b1, p_h1, BT, Hh, OBSn, OBSn, OBSn, Hh);
        col_stats<<<Hh / 32, statsBlk>>>(p_h1, BT, Hh, p_m, p_v);
        int total = BT * Hh;
        bn_apply<<<(total + 255) / 256, blk>>>(p_h1, p_h1, p_m, p_v, enc_g1, enc_bt1, total, Hh, 1);
    }
    // ---- encoder layer 2: x = BN(h1@W2^T+b2) ----
    {
        dim3 grid(Dd / 128, BT / 128);
        sgemm_abt<128, 8><<<grid, blk>>>(p_h1, enc_w2, enc_b2, p_x, BT, Dd, Hh, Hh, Hh, Dd);
        col_stats<<<Dd / 32, statsBlk>>>(p_x, BT, Dd, p_m, p_v);
        int total = BT * Dd;
        bn_apply<<<(total + 255) / 256, blk>>>(p_x, p_x, p_m, p_v, enc_g2, enc_bt2, total, Dd, 0);
    }
    // ---- gi = x @ wih^T + bih (all timesteps at once) ----
    {
        dim3 grid(3 * Dd / 128, BT / 128);
        sgemm_abt<128, 8><<<grid, blk>>>(p_x, gru_wih, gru_bih, p_gi, BT, 3 * Dd, Dd, Dd, Dd, 3 * Dd);
    }
    // ---- recurrent scan: one GEMM + one gate kernel per step ----
    zero_h<<<(Bb * Dd + 255) / 256, blk>>>();
    {
        dim3 gridS(4 * Dd / 128, Bb / 64);   // (32, 4) = 128 blocks
        for (int t = 0; t < Tt; t++) {
            sgemm_abt<64, 4><<<gridS, blk>>>(p_h, p_ws, nullptr, p_G,
                                             Bb, 4 * Dd, Dd, Dd, Dd, 4 * Dd);
            gru_gate2<<<(Bb * Dd + 255) / 256, blk>>>(actions, je_w, je_b, t);
        }
    }
    // ---- gumbel softmax: logits -> out[0:], z -> out[BZ:], g_z ----
    gumbel_softmax_k<<<Bb * ZLn, ZDn>>>(out);
    // ---- decoder layer 1 ----
    {
        dim3 grid(Hh / 128, Bb / 64);
        sgemm_abt<64, 4><<<grid, blk>>>(p_z, dec_w1, dec_b1, p_d1, Bb, Hh, Dd, Dd, Dd, Hh);
        col_stats<<<Hh / 32, statsBlk>>>(p_d1, Bb, Hh, p_m, p_v);
        int total = Bb * Hh;
        bn_apply<<<(total + 255) / 256, blk>>>(p_d1, p_d1, p_m, p_v, dec_g1, dec_bt1, total, Hh, 1);
    }
    // ---- decoder layer 2 -> x_hat at out[2*BZ:] ----
    {
        dim3 grid(OBSn / 128, Bb / 64);
        sgemm_abt<64, 4><<<grid, blk>>>(p_d1, dec_w2, dec_b2, p_d2, Bb, OBSn, Hh, Hh, Hh, OBSn);
        col_stats<<<OBSn / 32, statsBlk>>>(p_d2, Bb, OBSn, p_m, p_v);
        int total = Bb * OBSn;
        bn_apply<<<(total + 255) / 256, blk>>>(p_d2, out + 2 * Bb * ZLn * ZDn,
                                               p_m, p_v, dec_g2, dec_bt2, total, OBSn, 0);
    }
}

// round 5
// speedup vs baseline: 3.4282x; 1.9646x over previous
#include <cuda_runtime.h>
#include <cuda_bf16.h>
#include <cstdint>

#define Bb   256
#define Tt   64
#define OBSn 4096
#define Dd   1024
#define Aa   8
#define Hh   2048
#define ZLn  4
#define ZDn  256
#define BT   (Bb*Tt)          // 16384
#define EPSf 1e-5f
#define JEW_LD (Dd + Aa)      // 1032

typedef __nv_bfloat16 bf16;

// ---------------- scratch (static device globals; no allocation) -------------
__device__ float g_h1[BT * Hh];
__device__ float g_x [BT * Dd];
__device__ float g_gi[BT * 3 * Dd];
__device__ float g_G [Bb * 4 * Dd];
__device__ float g_h [Bb * Dd];
__device__ float g_z [Bb * ZLn * ZDn];
__device__ float g_d1[Bb * Hh];
__device__ float g_d2[Bb * OBSn];
__device__ float g_mean[4096];
__device__ float g_var [4096];
__device__ float g_wscan[4 * Dd * Dd];
__device__ float g_M2[3 * Dd * Aa];
__device__ float g_c [3 * Dd];

// bf16 hi/lo split buffers
__device__ bf16 g_obsh[BT * OBSn], g_obsl[BT * OBSn];
__device__ bf16 g_w1h [Hh * OBSn], g_w1l [Hh * OBSn];
__device__ bf16 g_h1h [BT * Hh],   g_h1l [BT * Hh];
__device__ bf16 g_w2h [Dd * Hh],   g_w2l [Dd * Hh];
__device__ bf16 g_xh  [BT * Dd],   g_xl  [BT * Dd];
__device__ bf16 g_wihh[3 * Dd * Dd], g_wihl[3 * Dd * Dd];
__device__ bf16 g_wsh [4 * Dd * Dd], g_wsl [4 * Dd * Dd];
__device__ bf16 g_hh  [Bb * Dd],   g_hl  [Bb * Dd];

// ======================= PTX helpers =========================================
__device__ __forceinline__ uint32_t smem_u32(const void* p) {
    uint32_t a;
    asm("{ .reg .u64 t; cvta.to.shared.u64 t, %1; cvt.u32.u64 %0, t; }"
        : "=r"(a) : "l"(p));
    return a;
}
__device__ __forceinline__ void cp16(uint32_t s, const void* g) {
    asm volatile("cp.async.cg.shared.global [%0], [%1], 16;" :: "r"(s), "l"(g));
}
__device__ __forceinline__ void cp_commit() {
    asm volatile("cp.async.commit_group;" ::: "memory");
}
__device__ __forceinline__ void cp_wait0() {
    asm volatile("cp.async.wait_group 0;" ::: "memory");
}
__device__ __forceinline__ void cp_wait1() {
    asm volatile("cp.async.wait_group 1;" ::: "memory");
}
__device__ __forceinline__ void ldm_x4(uint32_t* r, uint32_t a) {
    asm volatile("ldmatrix.sync.aligned.m8n8.x4.shared.b16 {%0,%1,%2,%3}, [%4];"
                 : "=r"(r[0]), "=r"(r[1]), "=r"(r[2]), "=r"(r[3]) : "r"(a));
}
__device__ __forceinline__ void ldm_x2(uint32_t* r, uint32_t a) {
    asm volatile("ldmatrix.sync.aligned.m8n8.x2.shared.b16 {%0,%1}, [%2];"
                 : "=r"(r[0]), "=r"(r[1]) : "r"(a));
}
__device__ __forceinline__ void mma_bf16(float* c, const uint32_t* a, const uint32_t* b) {
    asm volatile("mma.sync.aligned.m16n8k16.row.col.f32.bf16.bf16.f32 "
                 "{%0,%1,%2,%3}, {%4,%5,%6,%7}, {%8,%9}, {%0,%1,%2,%3};"
                 : "+f"(c[0]), "+f"(c[1]), "+f"(c[2]), "+f"(c[3])
                 : "r"(a[0]), "r"(a[1]), "r"(a[2]), "r"(a[3]),
                   "r"(b[0]), "r"(b[1]));
}

// =================== HMMA hi/lo-split GEMM: C = A @ B^T (+bias) ==============
// Ah/Al: M x K bf16 (ld=K); Bh/Bl: N x K bf16 (ld=K); C: M x N fp32.
// M%128==0 (scan M=256 ok), N%128==0, K%16==0.
// Grid (N/128, M/128), 256 threads. Static smem = 48KB exactly.
#define MLD 24   // 16 cols padded to 24 (48B rows -> conflict-free ldmatrix)

__global__ void __launch_bounds__(256)
mma_gemm(const bf16* __restrict__ Ah, const bf16* __restrict__ Al,
         const bf16* __restrict__ Bh, const bf16* __restrict__ Bl,
         const float* __restrict__ bias, float* __restrict__ C,
         int M, int N, int K)
{
    __shared__ bf16 sm[2][4][128 * MLD];   // [stage][Ah,Al,Bh,Bl]

    const int tid = threadIdx.x;
    const int wid = tid >> 5, lane = tid & 31;
    const int wm = wid >> 2, wn = wid & 3;          // 2 x 4 warp grid
    const int rowBase = blockIdx.y * 128, colBase = blockIdx.x * 128;
    const int NC = K >> 4;
    const int lrow = tid >> 1;                      // 0..127
    const int lseg = (tid & 1) << 3;                // 0 or 8 (bf16 elems)

    float acc[4][4][4];
#pragma unroll
    for (int i = 0; i < 4; i++)
#pragma unroll
        for (int j = 0; j < 4; j++)
#pragma unroll
            for (int k = 0; k < 4; k++) acc[i][j][k] = 0.f;

    const bf16* srcs[4] = { Ah, Al, Bh, Bl };
    const int   rbs [4] = { rowBase, rowBase, colBase, colBase };

    auto load = [&](int c, int st) {
        const int koff = c << 4;
#pragma unroll
        for (int tI = 0; tI < 4; tI++) {
            uint32_t s = smem_u32(&sm[st][tI][lrow * MLD + lseg]);
            cp16(s, srcs[tI] + (size_t)(rbs[tI] + lrow) * K + koff + lseg);
        }
        cp_commit();
    };

    load(0, 0);
    int st = 0;
    for (int c = 0; c < NC; c++) {
        const bool more = (c + 1) < NC;
        if (more) { load(c + 1, st ^ 1); cp_wait1(); }
        else      { cp_wait0(); }
        __syncthreads();

        uint32_t a[2][4][4];
        uint32_t b[2][4][2];
#pragma unroll
        for (int t = 0; t < 2; t++) {
            const bf16* base = sm[st][t];
#pragma unroll
            for (int mt = 0; mt < 4; mt++) {
                int r = wm * 64 + mt * 16 + (lane & 15);
                int cc = (lane >> 4) << 3;
                ldm_x4(a[t][mt], smem_u32(base + r * MLD + cc));
            }
        }
#pragma unroll
        for (int t = 0; t < 2; t++) {
            const bf16* base = sm[st][2 + t];
#pragma unroll
            for (int nt = 0; nt < 4; nt++) {
                int r = wn * 32 + nt * 8 + (lane & 7);
                int cc = ((lane >> 3) & 1) << 3;
                ldm_x2(b[t][nt], smem_u32(base + r * MLD + cc));
            }
        }
#pragma unroll
        for (int mt = 0; mt < 4; mt++)
#pragma unroll
            for (int nt = 0; nt < 4; nt++) {
                mma_bf16(acc[mt][nt], a[0][mt], b[0][nt]);   // Ah*Bh
                mma_bf16(acc[mt][nt], a[0][mt], b[1][nt]);   // Ah*Bl
                mma_bf16(acc[mt][nt], a[1][mt], b[0][nt]);   // Al*Bh
            }
        __syncthreads();
        st ^= 1;
    }

    // epilogue
#pragma unroll
    for (int mt = 0; mt < 4; mt++) {
        const int row = rowBase + wm * 64 + mt * 16 + (lane >> 2);
#pragma unroll
        for (int nt = 0; nt < 4; nt++) {
            const int col = colBase + wn * 32 + nt * 8 + (lane & 3) * 2;
            float b0 = bias ? bias[col] : 0.f;
            float b1 = bias ? bias[col + 1] : 0.f;
            *(float2*)(C + (size_t)row * N + col) =
                make_float2(acc[mt][nt][0] + b0, acc[mt][nt][1] + b1);
            *(float2*)(C + (size_t)(row + 8) * N + col) =
                make_float2(acc[mt][nt][2] + b0, acc[mt][nt][3] + b1);
        }
    }
}

// =============== hi/lo conversion: X fp32 -> Xh + Xl bf16 ====================
__global__ void cvt_hl(const float* __restrict__ X, bf16* __restrict__ Xh,
                       bf16* __restrict__ Xl, int n4)
{
    int i = blockIdx.x * blockDim.x + threadIdx.x;
    if (i >= n4) return;
    float4 v = ((const float4*)X)[i];
    bf16 h0 = __float2bfloat16(v.x), h1 = __float2bfloat16(v.y);
    bf16 h2 = __float2bfloat16(v.z), h3 = __float2bfloat16(v.w);
    float l0 = v.x - __bfloat162float(h0), l1 = v.y - __bfloat162float(h1);
    float l2 = v.z - __bfloat162float(h2), l3 = v.w - __bfloat162float(h3);
    __nv_bfloat162* H = (__nv_bfloat162*)Xh;
    __nv_bfloat162* L = (__nv_bfloat162*)Xl;
    H[2 * i]     = __nv_bfloat162(h0, h1);
    H[2 * i + 1] = __nv_bfloat162(h2, h3);
    L[2 * i]     = __nv_bfloat162(__float2bfloat16(l0), __float2bfloat16(l1));
    L[2 * i + 1] = __nv_bfloat162(__float2bfloat16(l2), __float2bfloat16(l3));
}

// =============== SIMT SGEMM (decoder / precompute) ===========================
#define BKd 8
template<int BMv, int TMv>
__global__ void __launch_bounds__(256)
sgemm_abt(const float* __restrict__ A, const float* __restrict__ Bm,
          const float* __restrict__ bias, float* __restrict__ C,
          int M, int N, int K, int lda, int ldb, int ldc)
{
    __shared__ float As[2][BKd][BMv];
    __shared__ float Bs[2][BKd][128];
    const int tid = threadIdx.x;
    const int tx = tid & 15, ty = tid >> 4;
    const int rowBase = blockIdx.y * BMv, colBase = blockIdx.x * 128;
    const int lrB = tid >> 1, lcB = (tid & 1) * 4;
    const bool loadA = (BMv == 128) ? true : (tid < 128);
    const int lrA = tid >> 1, lcA = (tid & 1) * 4;
    const float* Aptr = A + (size_t)(rowBase + lrA) * lda + lcA;
    const float* Bptr = Bm + (size_t)(colBase + lrB) * ldb + lcB;
    float acc[TMv][8];
#pragma unroll
    for (int i = 0; i < TMv; i++)
#pragma unroll
        for (int j = 0; j < 8; j++) acc[i][j] = 0.f;
    {
        float4 bv = *(const float4*)(Bptr);
        Bs[0][lcB+0][lrB]=bv.x; Bs[0][lcB+1][lrB]=bv.y;
        Bs[0][lcB+2][lrB]=bv.z; Bs[0][lcB+3][lrB]=bv.w;
        if (loadA) {
            float4 av = *(const float4*)(Aptr);
            As[0][lcA+0][lrA]=av.x; As[0][lcA+1][lrA]=av.y;
            As[0][lcA+2][lrA]=av.z; As[0][lcA+3][lrA]=av.w;
        }
    }
    __syncthreads();
    int buf = 0;
    for (int k0 = 0; k0 < K; k0 += BKd) {
        const bool more = (k0 + BKd) < K;
        float4 av2, bv2;
        if (more) {
            bv2 = *(const float4*)(Bptr + k0 + BKd);
            if (loadA) av2 = *(const float4*)(Aptr + k0 + BKd);
        }
#pragma unroll
        for (int kk = 0; kk < BKd; kk++) {
            float a[TMv], b[8];
#pragma unroll
            for (int i = 0; i < TMv; i++) a[i] = As[buf][kk][ty*TMv+i];
#pragma unroll
            for (int j = 0; j < 8; j++) b[j] = Bs[buf][kk][tx*8+j];
#pragma unroll
            for (int i = 0; i < TMv; i++)
#pragma unroll
                for (int j = 0; j < 8; j++)
                    acc[i][j] = fmaf(a[i], b[j], acc[i][j]);
        }
        if (more) {
            const int nb = buf ^ 1;
            Bs[nb][lcB+0][lrB]=bv2.x; Bs[nb][lcB+1][lrB]=bv2.y;
            Bs[nb][lcB+2][lrB]=bv2.z; Bs[nb][lcB+3][lrB]=bv2.w;
            if (loadA) {
                As[nb][lcA+0][lrA]=av2.x; As[nb][lcA+1][lrA]=av2.y;
                As[nb][lcA+2][lrA]=av2.z; As[nb][lcA+3][lrA]=av2.w;
            }
            __syncthreads();
            buf = nb;
        }
    }
#pragma unroll
    for (int i = 0; i < TMv; i++) {
        const int r = rowBase + ty * TMv + i;
#pragma unroll
        for (int j = 0; j < 8; j++) {
            const int c = colBase + tx * 8 + j;
            float bv = bias ? bias[c] : 0.f;
            C[(size_t)r * ldc + c] = acc[i][j] + bv;
        }
    }
}

__global__ void __launch_bounds__(256)
sgemm_ab(const float* __restrict__ A, const float* __restrict__ Bm,
         float* __restrict__ C, int M, int N, int K, int lda, int ldb, int ldc)
{
    __shared__ float As[BKd][128];
    __shared__ float Bs[BKd][128];
    const int tid = threadIdx.x;
    const int tx = tid & 15, ty = tid >> 4;
    const int rowBase = blockIdx.y * 128, colBase = blockIdx.x * 128;
    const int lrA = tid >> 1, lcA = (tid & 1) * 4;
    const int kkB = tid >> 5, c4B = (tid & 31) * 4;
    const float* Aptr = A + (size_t)(rowBase + lrA) * lda + lcA;
    const float* Bptr = Bm + (size_t)kkB * ldb + colBase + c4B;
    float acc[8][8];
#pragma unroll
    for (int i = 0; i < 8; i++)
#pragma unroll
        for (int j = 0; j < 8; j++) acc[i][j] = 0.f;
    for (int k0 = 0; k0 < K; k0 += BKd) {
        float4 av = *(const float4*)(Aptr + k0);
        float4 bv = *(const float4*)(Bptr + (size_t)k0 * ldb);
        As[lcA+0][lrA]=av.x; As[lcA+1][lrA]=av.y;
        As[lcA+2][lrA]=av.z; As[lcA+3][lrA]=av.w;
        *(float4*)&Bs[kkB][c4B] = bv;
        __syncthreads();
#pragma unroll
        for (int kk = 0; kk < BKd; kk++) {
            float a[8], b[8];
#pragma unroll
            for (int i = 0; i < 8; i++) a[i] = As[kk][ty*8+i];
#pragma unroll
            for (int j = 0; j < 8; j++) b[j] = Bs[kk][tx*8+j];
#pragma unroll
            for (int i = 0; i < 8; i++)
#pragma unroll
                for (int j = 0; j < 8; j++)
                    acc[i][j] = fmaf(a[i], b[j], acc[i][j]);
        }
        __syncthreads();
    }
#pragma unroll
    for (int i = 0; i < 8; i++) {
        const int r = rowBase + ty * 8 + i;
#pragma unroll
        for (int j = 0; j < 8; j++)
            C[(size_t)r * ldc + colBase + tx * 8 + j] = acc[i][j];
    }
}

__global__ void copy_jew(const float* __restrict__ je_w)
{
    int idx = blockIdx.x * blockDim.x + threadIdx.x;
    if (idx >= Dd * Dd) return;
    int j = idx >> 10, k = idx & 1023;
    g_wscan[(size_t)(3 * Dd + j) * Dd + k] = je_w[(size_t)j * JEW_LD + k];
}

__global__ void __launch_bounds__(128)
m2c_k(const float* __restrict__ whh, const float* __restrict__ je_w,
      const float* __restrict__ je_b, const float* __restrict__ bhh)
{
    const int i = blockIdx.x;
    const int t = threadIdx.x;
    float acc[9];
#pragma unroll
    for (int j = 0; j < 9; j++) acc[j] = 0.f;
    for (int k = t; k < Dd; k += 128) {
        float w = whh[(size_t)i * Dd + k];
        const float* jr = je_w + (size_t)k * JEW_LD + Dd;
#pragma unroll
        for (int j = 0; j < 8; j++) acc[j] = fmaf(w, jr[j], acc[j]);
        acc[8] = fmaf(w, je_b[k], acc[8]);
    }
    __shared__ float sh[9][128];
#pragma unroll
    for (int j = 0; j < 9; j++) sh[j][t] = acc[j];
    __syncthreads();
    for (int s = 64; s > 0; s >>= 1) {
        if (t < s)
#pragma unroll
            for (int j = 0; j < 9; j++) sh[j][t] += sh[j][t + s];
        __syncthreads();
    }
    if (t == 0) {
#pragma unroll
        for (int j = 0; j < 8; j++) g_M2[i * 8 + j] = sh[j][0];
        g_c[i] = sh[8][0] + bhh[i];
    }
}

// ---------------- batch stats + BN ------------------------------------------
__global__ void col_stats(const float* __restrict__ X, int M, int N,
                          float* __restrict__ mean, float* __restrict__ var)
{
    const int c = blockIdx.x * 32 + threadIdx.x;
    const int ry = threadIdx.y;
    float s = 0.f, s2 = 0.f;
    for (int r = ry; r < M; r += 8) {
        float v = X[(size_t)r * N + c];
        s += v; s2 += v * v;
    }
    __shared__ float sh[8][32], sh2[8][32];
    sh[ry][threadIdx.x] = s; sh2[ry][threadIdx.x] = s2;
    __syncthreads();
    if (ry == 0) {
#pragma unroll
        for (int y = 1; y < 8; y++) { s += sh[y][threadIdx.x]; s2 += sh2[y][threadIdx.x]; }
        float m = s / (float)M;
        mean[c] = m;
        var[c]  = s2 / (float)M - m * m;
    }
}

__global__ void bn_apply(const float* __restrict__ X, float* __restrict__ Y,
                         const float* __restrict__ mean, const float* __restrict__ var,
                         const float* __restrict__ g, const float* __restrict__ beta,
                         int total, int N, int relu)
{
    int idx = blockIdx.x * blockDim.x + threadIdx.x;
    if (idx >= total) return;
    int c = idx % N;
    float v = g[c] * (X[idx] - mean[c]) * rsqrtf(var[c] + EPSf) + beta[c];
    if (relu) v = fmaxf(v, 0.f);
    Y[idx] = v;
}

__global__ void bn_apply_cvt(const float* __restrict__ X, float* __restrict__ Yf,
                             bf16* __restrict__ Yh, bf16* __restrict__ Yl,
                             const float* __restrict__ mean, const float* __restrict__ var,
                             const float* __restrict__ g, const float* __restrict__ beta,
                             int total4, int N, int relu)
{
    int i = blockIdx.x * blockDim.x + threadIdx.x;
    if (i >= total4) return;
    int c0 = (i * 4) % N;
    float4 v = ((const float4*)X)[i];
    float o[4] = { v.x, v.y, v.z, v.w };
#pragma unroll
    for (int j = 0; j < 4; j++) {
        int c = c0 + j;
        float t = g[c] * (o[j] - mean[c]) * rsqrtf(var[c] + EPSf) + beta[c];
        if (relu) t = fmaxf(t, 0.f);
        o[j] = t;
    }
    if (Yf) ((float4*)Yf)[i] = make_float4(o[0], o[1], o[2], o[3]);
    bf16 h0 = __float2bfloat16(o[0]), h1 = __float2bfloat16(o[1]);
    bf16 h2 = __float2bfloat16(o[2]), h3 = __float2bfloat16(o[3]);
    __nv_bfloat162* H = (__nv_bfloat162*)Yh;
    __nv_bfloat162* L = (__nv_bfloat162*)Yl;
    H[2*i]   = __nv_bfloat162(h0, h1);
    H[2*i+1] = __nv_bfloat162(h2, h3);
    L[2*i]   = __nv_bfloat162(__float2bfloat16(o[0] - __bfloat162float(h0)),
                              __float2bfloat16(o[1] - __bfloat162float(h1)));
    L[2*i+1] = __nv_bfloat162(__float2bfloat16(o[2] - __bfloat162float(h2)),
                              __float2bfloat16(o[3] - __bfloat162float(h3)));
}

// ---------------- scan ------------------------------------------------------
__global__ void zero_h() {
    int idx = blockIdx.x * blockDim.x + threadIdx.x;
    if (idx < Bb * Dd) {
        g_h[idx] = 0.f;
        g_hh[idx] = __float2bfloat16(0.f);
        g_hl[idx] = __float2bfloat16(0.f);
    }
}

__device__ __forceinline__ float sigmoidf_(float x) { return 1.f / (1.f + expf(-x)); }

__global__ void gru_gate2(const float* __restrict__ actions,
                          const float* __restrict__ je_w,
                          const float* __restrict__ je_b, int t)
{
    int idx = blockIdx.x * blockDim.x + threadIdx.x;
    if (idx >= Bb * Dd) return;
    int b = idx >> 10;
    int d = idx & 1023;
    int row = b * Tt + t;

    const float* a = actions + (size_t)row * Aa;
    float av[8];
#pragma unroll
    for (int j = 0; j < 8; j++) av[j] = a[j];

    const float* G = g_G + (size_t)b * (4 * Dd);

    float hr = G[d]          + g_c[d];
    float hz = G[Dd + d]     + g_c[Dd + d];
    float hn = G[2 * Dd + d] + g_c[2 * Dd + d];
    float hj = G[3 * Dd + d] + je_b[d];
    const float* m2r = g_M2 + (size_t)d * 8;
    const float* m2z = g_M2 + (size_t)(Dd + d) * 8;
    const float* m2n = g_M2 + (size_t)(2 * Dd + d) * 8;
    const float* jea = je_w + (size_t)d * JEW_LD + Dd;
#pragma unroll
    for (int j = 0; j < 8; j++) {
        hr = fmaf(av[j], m2r[j], hr);
        hz = fmaf(av[j], m2z[j], hz);
        hn = fmaf(av[j], m2n[j], hn);
        hj = fmaf(av[j], jea[j], hj);
    }

    const float* gi = g_gi + (size_t)row * (3 * Dd);
    float r = sigmoidf_(gi[d] + hr);
    float z = sigmoidf_(gi[Dd + d] + hz);
    float n = tanhf(gi[2 * Dd + d] + r * hn);
    float xv = g_x[(size_t)row * Dd + d];
    float hnew = (1.f - z) * n + z * hj + xv;
    g_h[idx] = hnew;
    bf16 hh = __float2bfloat16(hnew);
    g_hh[idx] = hh;
    g_hl[idx] = __float2bfloat16(hnew - __bfloat162float(hh));
}

// ---------------- threefry2x32-20 (JAX partitionable) ------------------------
__device__ __forceinline__ uint32_t rotl32_(uint32_t x, int r) {
    return (x << r) | (x >> (32 - r));
}
__device__ __forceinline__ void threefry2x32_(uint32_t k0, uint32_t k1,
                                              uint32_t& x0, uint32_t& x1)
{
    const uint32_t k2 = k0 ^ k1 ^ 0x1BD11BDAu;
    x0 += k0; x1 += k1;
#define TF_R4(a,b,c,d) \
    x0 += x1; x1 = rotl32_(x1, a); x1 ^= x0; \
    x0 += x1; x1 = rotl32_(x1, b); x1 ^= x0; \
    x0 += x1; x1 = rotl32_(x1, c); x1 ^= x0; \
    x0 += x1; x1 = rotl32_(x1, d); x1 ^= x0;
    TF_R4(13,15,26,6)  x0 += k1; x1 += k2 + 1u;
    TF_R4(17,29,16,24) x0 += k2; x1 += k0 + 2u;
    TF_R4(13,15,26,6)  x0 += k0; x1 += k1 + 3u;
    TF_R4(17,29,16,24) x0 += k1; x1 += k2 + 4u;
    TF_R4(13,15,26,6)  x0 += k2; x1 += k0 + 5u;
#undef TF_R4
}

__global__ void gumbel_softmax_k(float* __restrict__ out)
{
    const int bl = blockIdx.x;
    const int d  = threadIdx.x;
    const int i  = bl * ZDn + d;
    const float logit = g_h[i];

    uint32_t c0 = 0u;
    uint32_t c1 = (uint32_t)i;
    threefry2x32_(0u, 42u, c0, c1);
    const uint32_t bits = c0 ^ c1;
    float f = __uint_as_float((bits >> 9) | 0x3f800000u) - 1.0f;
    const float tiny = 1.1754943508222875e-38f;
    float u = fmaxf(f * (1.0f - tiny) + tiny, tiny);
    float gum = -logf(-logf(u));

    float v = logit + gum;

    __shared__ float red[ZDn];
    red[d] = v; __syncthreads();
    for (int s = ZDn / 2; s > 0; s >>= 1) {
        if (d < s) red[d] = fmaxf(red[d], red[d + s]);
        __syncthreads();
    }
    float mx = red[0];
    __syncthreads();
    float e = expf(v - mx);
    red[d] = e; __syncthreads();
    for (int s = ZDn / 2; s > 0; s >>= 1) {
        if (d < s) red[d] += red[d + s];
        __syncthreads();
    }
    float z = e / red[0];

    out[i] = logit;
    out[Bb * ZLn * ZDn + i] = z;
    g_z[i] = z;
}

// ---------------- launch ------------------------------------------------------
static inline float* symf(const void* s) {
    void* p = nullptr;
    cudaGetSymbolAddress(&p, s);
    return (float*)p;
}
static inline bf16* symb(const void* s) {
    void* p = nullptr;
    cudaGetSymbolAddress(&p, s);
    return (bf16*)p;
}

extern "C" void kernel_launch(void* const* d_in, const int* in_sizes, int n_in,
                              void* d_out, int out_size)
{
    (void)in_sizes; (void)n_in; (void)out_size;
    const float* obs      = (const float*)d_in[0];
    const float* actions  = (const float*)d_in[1];
    const float* enc_w1   = (const float*)d_in[2];
    const float* enc_b1   = (const float*)d_in[3];
    const float* enc_g1   = (const float*)d_in[4];
    const float* enc_bt1  = (const float*)d_in[5];
    const float* enc_w2   = (const float*)d_in[6];
    const float* enc_b2   = (const float*)d_in[7];
    const float* enc_g2   = (const float*)d_in[8];
    const float* enc_bt2  = (const float*)d_in[9];
    const float* je_w     = (const float*)d_in[10];
    const float* je_b     = (const float*)d_in[11];
    const float* gru_wih  = (const float*)d_in[12];
    const float* gru_bih  = (const float*)d_in[13];
    const float* gru_whh  = (const float*)d_in[14];
    const float* gru_bhh  = (const float*)d_in[15];
    const float* dec_w1   = (const float*)d_in[16];
    const float* dec_b1   = (const float*)d_in[17];
    const float* dec_g1   = (const float*)d_in[18];
    const float* dec_bt1  = (const float*)d_in[19];
    const float* dec_w2   = (const float*)d_in[20];
    const float* dec_b2   = (const float*)d_in[21];
    const float* dec_g2   = (const float*)d_in[22];
    const float* dec_bt2  = (const float*)d_in[23];
    float* out = (float*)d_out;

    float* p_h1 = symf(g_h1);
    float* p_x  = symf(g_x);
    float* p_gi = symf(g_gi);
    float* p_G  = symf(g_G);
    float* p_z  = symf(g_z);
    float* p_d1 = symf(g_d1);
    float* p_d2 = symf(g_d2);
    float* p_m  = symf(g_mean);
    float* p_v  = symf(g_var);
    float* p_ws = symf(g_wscan);

    bf16 *p_obsh = symb(g_obsh), *p_obsl = symb(g_obsl);
    bf16 *p_w1h = symb(g_w1h), *p_w1l = symb(g_w1l);
    bf16 *p_h1h = symb(g_h1h), *p_h1l = symb(g_h1l);
    bf16 *p_w2h = symb(g_w2h), *p_w2l = symb(g_w2l);
    bf16 *p_xh = symb(g_xh), *p_xl = symb(g_xl);
    bf16 *p_wihh = symb(g_wihh), *p_wihl = symb(g_wihl);
    bf16 *p_wsh = symb(g_wsh), *p_wsl = symb(g_wsl);
    bf16 *p_hh = symb(g_hh), *p_hl = symb(g_hl);

    dim3 blk(256);
    dim3 statsBlk(32, 8);

    // ---- input/weight conversions ----
    cvt_hl<<<(BT * OBSn / 4 + 255) / 256, blk>>>(obs, p_obsh, p_obsl, BT * OBSn / 4);
    cvt_hl<<<(Hh * OBSn / 4 + 255) / 256, blk>>>(enc_w1, p_w1h, p_w1l, Hh * OBSn / 4);
    cvt_hl<<<(Dd * Hh / 4 + 255) / 256, blk>>>(enc_w2, p_w2h, p_w2l, Dd * Hh / 4);
    cvt_hl<<<(3 * Dd * Dd / 4 + 255) / 256, blk>>>(gru_wih, p_wihh, p_wihl, 3 * Dd * Dd / 4);

    // ---- precompute scan operators ----
    {
        dim3 grid(Dd / 128, 3 * Dd / 128);
        sgemm_ab<<<grid, blk>>>(gru_whh, je_w, p_ws, 3 * Dd, Dd, Dd, Dd, JEW_LD, Dd);
        copy_jew<<<(Dd * Dd + 255) / 256, blk>>>(je_w);
        m2c_k<<<3 * Dd, 128>>>(gru_whh, je_w, je_b, gru_bhh);
        cvt_hl<<<(4 * Dd * Dd / 4 + 255) / 256, blk>>>(p_ws, p_wsh, p_wsl, 4 * Dd * Dd / 4);
    }

    // ---- encoder layer 1 (HMMA) ----
    {
        dim3 grid(Hh / 128, BT / 128);
        mma_gemm<<<grid, blk>>>(p_obsh, p_obsl, p_w1h, p_w1l, enc_b1, p_h1, BT, Hh, OBSn);
        col_stats<<<Hh / 32, statsBlk>>>(p_h1, BT, Hh, p_m, p_v);
        bn_apply_cvt<<<(BT * Hh / 4 + 255) / 256, blk>>>(p_h1, nullptr, p_h1h, p_h1l,
                                                         p_m, p_v, enc_g1, enc_bt1,
                                                         BT * Hh / 4, Hh, 1);
    }
    // ---- encoder layer 2 (HMMA) ----
    {
        dim3 grid(Dd / 128, BT / 128);
        mma_gemm<<<grid, blk>>>(p_h1h, p_h1l, p_w2h, p_w2l, enc_b2, p_x, BT, Dd, Hh);
        col_stats<<<Dd / 32, statsBlk>>>(p_x, BT, Dd, p_m, p_v);
        bn_apply_cvt<<<(BT * Dd / 4 + 255) / 256, blk>>>(p_x, p_x, p_xh, p_xl,
                                                         p_m, p_v, enc_g2, enc_bt2,
                                                         BT * Dd / 4, Dd, 0);
    }
    // ---- gi (HMMA) ----
    {
        dim3 grid(3 * Dd / 128, BT / 128);
        mma_gemm<<<grid, blk>>>(p_xh, p_xl, p_wihh, p_wihl, gru_bih, p_gi, BT, 3 * Dd, Dd);
    }
    // ---- recurrent scan (HMMA GEMM per step) ----
    zero_h<<<(Bb * Dd + 255) / 256, blk>>>();
    {
        dim3 gridS(4 * Dd / 128, Bb / 128);   // (32, 2)
        for (int t = 0; t < Tt; t++) {
            mma_gemm<<<gridS, blk>>>(p_hh, p_hl, p_wsh, p_wsl, nullptr, p_G,
                                     Bb, 4 * Dd, Dd);
            gru_gate2<<<(Bb * Dd + 255) / 256, blk>>>(actions, je_w, je_b, t);
        }
    }
    // ---- gumbel softmax ----
    gumbel_softmax_k<<<Bb * ZLn, ZDn>>>(out);
    // ---- decoder (SIMT) ----
    {
        dim3 grid(Hh / 128, Bb / 64);
        sgemm_abt<64, 4><<<grid, blk>>>(p_z, dec_w1, dec_b1, p_d1, Bb, Hh, Dd, Dd, Dd, Hh);
        col_stats<<<Hh / 32, statsBlk>>>(p_d1, Bb, Hh, p_m, p_v);
        int total = Bb * Hh;
        bn_apply<<<(total + 255) / 256, blk>>>(p_d1, p_d1, p_m, p_v, dec_g1, dec_bt1, total, Hh, 1);
    }
    {
        dim3 grid(OBSn / 128, Bb / 64);
        sgemm_abt<64, 4><<<grid, blk>>>(p_d1, dec_w2, dec_b2, p_d2, Bb, OBSn, Hh, Hh, Hh, OBSn);
        col_stats<<<OBSn / 32, statsBlk>>>(p_d2, Bb, OBSn, p_m, p_v);
        int total = Bb * OBSn;
        bn_apply<<<(total + 255) / 256, blk>>>(p_d2, out + 2 * Bb * ZLn * ZDn,
                                               p_m, p_v, dec_g2, dec_bt2, total, OBSn, 0);
    }
}

// round 6
// speedup vs baseline: 3.7099x; 1.0821x over previous
#include <cuda_runtime.h>
#include <cuda_bf16.h>
#include <cstdint>

#define Bb   256
#define Tt   64
#define OBSn 4096
#define Dd   1024
#define Aa   8
#define Hh   2048
#define ZLn  4
#define ZDn  256
#define BT   (Bb*Tt)          // 16384
#define EPSf 1e-5f
#define JEW_LD (Dd + Aa)      // 1032

typedef __nv_bfloat16 bf16;

// ---------------- scratch (static device globals; no allocation) -------------
__device__ float g_h1[BT * Hh];
__device__ float g_x [BT * Dd];
__device__ float g_gi[BT * 3 * Dd];
__device__ float g_G [Bb * 4 * Dd];
__device__ float g_h [Bb * Dd];
__device__ float g_z [Bb * ZLn * ZDn];
__device__ float g_d1[Bb * Hh];
__device__ float g_d2[Bb * OBSn];
__device__ float g_mean[4096];
__device__ float g_var [4096];
__device__ float g_wscan[4 * Dd * Dd];
__device__ float g_M2[3 * Dd * Aa];
__device__ float g_c [3 * Dd];

// bf16 hi/lo split buffers
__device__ bf16 g_obsh[BT * OBSn], g_obsl[BT * OBSn];
__device__ bf16 g_w1h [Hh * OBSn], g_w1l [Hh * OBSn];
__device__ bf16 g_h1h [BT * Hh],   g_h1l [BT * Hh];
__device__ bf16 g_w2h [Dd * Hh],   g_w2l [Dd * Hh];
__device__ bf16 g_xh  [BT * Dd],   g_xl  [BT * Dd];
__device__ bf16 g_wihh[3 * Dd * Dd], g_wihl[3 * Dd * Dd];
__device__ bf16 g_wsh [4 * Dd * Dd], g_wsl [4 * Dd * Dd];
__device__ bf16 g_hh  [Bb * Dd],   g_hl  [Bb * Dd];
__device__ bf16 g_zh  [Bb * Dd],   g_zl  [Bb * Dd];
__device__ bf16 g_d1h [Bb * Hh],   g_d1l [Bb * Hh];
__device__ bf16 g_dw1h[Hh * Dd],   g_dw1l[Hh * Dd];
__device__ bf16 g_dw2h[OBSn * Hh], g_dw2l[OBSn * Hh];

// ======================= PTX helpers =========================================
__device__ __forceinline__ uint32_t smem_u32(const void* p) {
    uint32_t a;
    asm("{ .reg .u64 t; cvta.to.shared.u64 t, %1; cvt.u32.u64 %0, t; }"
        : "=r"(a) : "l"(p));
    return a;
}
__device__ __forceinline__ void cp16(uint32_t s, const void* g) {
    asm volatile("cp.async.cg.shared.global [%0], [%1], 16;" :: "r"(s), "l"(g));
}
__device__ __forceinline__ void cp_commit() {
    asm volatile("cp.async.commit_group;" ::: "memory");
}
__device__ __forceinline__ void cp_wait0() {
    asm volatile("cp.async.wait_group 0;" ::: "memory");
}
__device__ __forceinline__ void cp_wait1() {
    asm volatile("cp.async.wait_group 1;" ::: "memory");
}
__device__ __forceinline__ void ldm_x4(uint32_t* r, uint32_t a) {
    asm volatile("ldmatrix.sync.aligned.m8n8.x4.shared.b16 {%0,%1,%2,%3}, [%4];"
                 : "=r"(r[0]), "=r"(r[1]), "=r"(r[2]), "=r"(r[3]) : "r"(a));
}
__device__ __forceinline__ void ldm_x2(uint32_t* r, uint32_t a) {
    asm volatile("ldmatrix.sync.aligned.m8n8.x2.shared.b16 {%0,%1}, [%2];"
                 : "=r"(r[0]), "=r"(r[1]) : "r"(a));
}
__device__ __forceinline__ void mma_bf16(float* c, const uint32_t* a, const uint32_t* b) {
    asm volatile("mma.sync.aligned.m16n8k16.row.col.f32.bf16.bf16.f32 "
                 "{%0,%1,%2,%3}, {%4,%5,%6,%7}, {%8,%9}, {%0,%1,%2,%3};"
                 : "+f"(c[0]), "+f"(c[1]), "+f"(c[2]), "+f"(c[3])
                 : "r"(a[0]), "r"(a[1]), "r"(a[2]), "r"(a[3]),
                   "r"(b[0]), "r"(b[1]));
}

// =================== HMMA hi/lo-split GEMM: C = A @ B^T (+bias) ==============
// KC=32, 2-stage cp.async, dynamic smem. Ah/Al: MxK, Bh/Bl: NxK (bf16, ld=K),
// C: MxN fp32. M%128==0, N%128==0, K%32==0. Grid (N/128, M/128), 256 threads.
#define LD2   40                       // 32 cols padded to 40 (80B rows)
#define TILE2 (128 * LD2)              // bf16 elems per tile
#define STAGE2 (4 * TILE2)             // Ah, Al, Bh, Bl
#define SM2_BYTES (2 * STAGE2 * 2)     // 81920

__global__ void __launch_bounds__(256)
mma_gemm(const bf16* __restrict__ Ah, const bf16* __restrict__ Al,
         const bf16* __restrict__ Bh, const bf16* __restrict__ Bl,
         const float* __restrict__ bias, float* __restrict__ C,
         int M, int N, int K)
{
    extern __shared__ bf16 sm2[];

    const int tid = threadIdx.x;
    const int wid = tid >> 5, lane = tid & 31;
    const int wm = wid >> 2, wn = wid & 3;          // 2 x 4 warp grid
    const int rowBase = blockIdx.y * 128, colBase = blockIdx.x * 128;
    const int NC = K >> 5;

    float acc[4][4][4];
#pragma unroll
    for (int i = 0; i < 4; i++)
#pragma unroll
        for (int j = 0; j < 4; j++)
#pragma unroll
            for (int k = 0; k < 4; k++) acc[i][j][k] = 0.f;

    const bf16* srcs[4] = { Ah, Al, Bh, Bl };
    const int   rbs [4] = { rowBase, rowBase, colBase, colBase };

    auto load = [&](int c, int st) {
        const int koff = c << 5;
        bf16* stp = sm2 + st * STAGE2;
#pragma unroll
        for (int tI = 0; tI < 4; tI++) {
#pragma unroll
            for (int i = 0; i < 2; i++) {
                int u = tid * 2 + i;                // 0..511
                int row = u >> 2;                   // 0..127
                int seg = (u & 3) << 3;             // 0,8,16,24
                cp16(smem_u32(stp + tI * TILE2 + row * LD2 + seg),
                     srcs[tI] + (size_t)(rbs[tI] + row) * K + koff + seg);
            }
        }
        cp_commit();
    };

    load(0, 0);
    int st = 0;
    for (int c = 0; c < NC; c++) {
        const bool more = (c + 1) < NC;
        if (more) { load(c + 1, st ^ 1); cp_wait1(); }
        else      { cp_wait0(); }
        __syncthreads();

        const bf16* stp = sm2 + st * STAGE2;
#pragma unroll
        for (int kh = 0; kh < 2; kh++) {
            const int kcol = kh << 4;
            uint32_t a[2][4][4];
            uint32_t b[2][4][2];
#pragma unroll
            for (int t = 0; t < 2; t++) {
                const bf16* base = stp + t * TILE2;
#pragma unroll
                for (int mt = 0; mt < 4; mt++) {
                    int r = wm * 64 + mt * 16 + (lane & 15);
                    int cc = kcol + ((lane >> 4) << 3);
                    ldm_x4(a[t][mt], smem_u32(base + r * LD2 + cc));
                }
            }
#pragma unroll
            for (int t = 0; t < 2; t++) {
                const bf16* base = stp + (2 + t) * TILE2;
#pragma unroll
                for (int nt = 0; nt < 4; nt++) {
                    int r = wn * 32 + nt * 8 + (lane & 7);
                    int cc = kcol + (((lane >> 3) & 1) << 3);
                    ldm_x2(b[t][nt], smem_u32(base + r * LD2 + cc));
                }
            }
#pragma unroll
            for (int mt = 0; mt < 4; mt++)
#pragma unroll
                for (int nt = 0; nt < 4; nt++) {
                    mma_bf16(acc[mt][nt], a[0][mt], b[0][nt]);   // Ah*Bh
                    mma_bf16(acc[mt][nt], a[0][mt], b[1][nt]);   // Ah*Bl
                    mma_bf16(acc[mt][nt], a[1][mt], b[0][nt]);   // Al*Bh
                }
        }
        __syncthreads();
        st ^= 1;
    }

    // epilogue
#pragma unroll
    for (int mt = 0; mt < 4; mt++) {
        const int row = rowBase + wm * 64 + mt * 16 + (lane >> 2);
#pragma unroll
        for (int nt = 0; nt < 4; nt++) {
            const int col = colBase + wn * 32 + nt * 8 + (lane & 3) * 2;
            float b0 = bias ? bias[col] : 0.f;
            float b1 = bias ? bias[col + 1] : 0.f;
            *(float2*)(C + (size_t)row * N + col) =
                make_float2(acc[mt][nt][0] + b0, acc[mt][nt][1] + b1);
            *(float2*)(C + (size_t)(row + 8) * N + col) =
                make_float2(acc[mt][nt][2] + b0, acc[mt][nt][3] + b1);
        }
    }
}

// =============== hi/lo conversion: X fp32 -> Xh + Xl bf16 ====================
__global__ void cvt_hl(const float* __restrict__ X, bf16* __restrict__ Xh,
                       bf16* __restrict__ Xl, int n4)
{
    int i = blockIdx.x * blockDim.x + threadIdx.x;
    if (i >= n4) return;
    float4 v = ((const float4*)X)[i];
    bf16 h0 = __float2bfloat16(v.x), h1 = __float2bfloat16(v.y);
    bf16 h2 = __float2bfloat16(v.z), h3 = __float2bfloat16(v.w);
    float l0 = v.x - __bfloat162float(h0), l1 = v.y - __bfloat162float(h1);
    float l2 = v.z - __bfloat162float(h2), l3 = v.w - __bfloat162float(h3);
    __nv_bfloat162* H = (__nv_bfloat162*)Xh;
    __nv_bfloat162* L = (__nv_bfloat162*)Xl;
    H[2 * i]     = __nv_bfloat162(h0, h1);
    H[2 * i + 1] = __nv_bfloat162(h2, h3);
    L[2 * i]     = __nv_bfloat162(__float2bfloat16(l0), __float2bfloat16(l1));
    L[2 * i + 1] = __nv_bfloat162(__float2bfloat16(l2), __float2bfloat16(l3));
}

// =============== SIMT GEMM (precompute only) ==================================
#define BKd 8
__global__ void __launch_bounds__(256)
sgemm_ab(const float* __restrict__ A, const float* __restrict__ Bm,
         float* __restrict__ C, int M, int N, int K, int lda, int ldb, int ldc)
{
    __shared__ float As[BKd][128];
    __shared__ float Bs[BKd][128];
    const int tid = threadIdx.x;
    const int tx = tid & 15, ty = tid >> 4;
    const int rowBase = blockIdx.y * 128, colBase = blockIdx.x * 128;
    const int lrA = tid >> 1, lcA = (tid & 1) * 4;
    const int kkB = tid >> 5, c4B = (tid & 31) * 4;
    const float* Aptr = A + (size_t)(rowBase + lrA) * lda + lcA;
    const float* Bptr = Bm + (size_t)kkB * ldb + colBase + c4B;
    float acc[8][8];
#pragma unroll
    for (int i = 0; i < 8; i++)
#pragma unroll
        for (int j = 0; j < 8; j++) acc[i][j] = 0.f;
    for (int k0 = 0; k0 < K; k0 += BKd) {
        float4 av = *(const float4*)(Aptr + k0);
        float4 bv = *(const float4*)(Bptr + (size_t)k0 * ldb);
        As[lcA+0][lrA]=av.x; As[lcA+1][lrA]=av.y;
        As[lcA+2][lrA]=av.z; As[lcA+3][lrA]=av.w;
        *(float4*)&Bs[kkB][c4B] = bv;
        __syncthreads();
#pragma unroll
        for (int kk = 0; kk < BKd; kk++) {
            float a[8], b[8];
#pragma unroll
            for (int i = 0; i < 8; i++) a[i] = As[kk][ty*8+i];
#pragma unroll
            for (int j = 0; j < 8; j++) b[j] = Bs[kk][tx*8+j];
#pragma unroll
            for (int i = 0; i < 8; i++)
#pragma unroll
                for (int j = 0; j < 8; j++)
                    acc[i][j] = fmaf(a[i], b[j], acc[i][j]);
        }
        __syncthreads();
    }
#pragma unroll
    for (int i = 0; i < 8; i++) {
        const int r = rowBase + ty * 8 + i;
#pragma unroll
        for (int j = 0; j < 8; j++)
            C[(size_t)r * ldc + colBase + tx * 8 + j] = acc[i][j];
    }
}

__global__ void copy_jew(const float* __restrict__ je_w)
{
    int idx = blockIdx.x * blockDim.x + threadIdx.x;
    if (idx >= Dd * Dd) return;
    int j = idx >> 10, k = idx & 1023;
    g_wscan[(size_t)(3 * Dd + j) * Dd + k] = je_w[(size_t)j * JEW_LD + k];
}

__global__ void __launch_bounds__(128)
m2c_k(const float* __restrict__ whh, const float* __restrict__ je_w,
      const float* __restrict__ je_b, const float* __restrict__ bhh)
{
    const int i = blockIdx.x;
    const int t = threadIdx.x;
    float acc[9];
#pragma unroll
    for (int j = 0; j < 9; j++) acc[j] = 0.f;
    for (int k = t; k < Dd; k += 128) {
        float w = whh[(size_t)i * Dd + k];
        const float* jr = je_w + (size_t)k * JEW_LD + Dd;
#pragma unroll
        for (int j = 0; j < 8; j++) acc[j] = fmaf(w, jr[j], acc[j]);
        acc[8] = fmaf(w, je_b[k], acc[8]);
    }
    __shared__ float sh[9][128];
#pragma unroll
    for (int j = 0; j < 9; j++) sh[j][t] = acc[j];
    __syncthreads();
    for (int s = 64; s > 0; s >>= 1) {
        if (t < s)
#pragma unroll
            for (int j = 0; j < 9; j++) sh[j][t] += sh[j][t + s];
        __syncthreads();
    }
    if (t == 0) {
#pragma unroll
        for (int j = 0; j < 8; j++) g_M2[i * 8 + j] = sh[j][0];
        g_c[i] = sh[8][0] + bhh[i];
    }
}

// ---------------- batch stats + BN ------------------------------------------
__global__ void col_stats(const float* __restrict__ X, int M, int N,
                          float* __restrict__ mean, float* __restrict__ var)
{
    const int c = blockIdx.x * 32 + threadIdx.x;
    const int ry = threadIdx.y;
    float s = 0.f, s2 = 0.f;
    for (int r = ry; r < M; r += 8) {
        float v = X[(size_t)r * N + c];
        s += v; s2 += v * v;
    }
    __shared__ float sh[8][32], sh2[8][32];
    sh[ry][threadIdx.x] = s; sh2[ry][threadIdx.x] = s2;
    __syncthreads();
    if (ry == 0) {
#pragma unroll
        for (int y = 1; y < 8; y++) { s += sh[y][threadIdx.x]; s2 += sh2[y][threadIdx.x]; }
        float m = s / (float)M;
        mean[c] = m;
        var[c]  = s2 / (float)M - m * m;
    }
}

__global__ void bn_apply(const float* __restrict__ X, float* __restrict__ Y,
                         const float* __restrict__ mean, const float* __restrict__ var,
                         const float* __restrict__ g, const float* __restrict__ beta,
                         int total, int N, int relu)
{
    int idx = blockIdx.x * blockDim.x + threadIdx.x;
    if (idx >= total) return;
    int c = idx % N;
    float v = g[c] * (X[idx] - mean[c]) * rsqrtf(var[c] + EPSf) + beta[c];
    if (relu) v = fmaxf(v, 0.f);
    Y[idx] = v;
}

__global__ void bn_apply_cvt(const float* __restrict__ X, float* __restrict__ Yf,
                             bf16* __restrict__ Yh, bf16* __restrict__ Yl,
                             const float* __restrict__ mean, const float* __restrict__ var,
                             const float* __restrict__ g, const float* __restrict__ beta,
                             int total4, int N, int relu)
{
    int i = blockIdx.x * blockDim.x + threadIdx.x;
    if (i >= total4) return;
    int c0 = (i * 4) % N;
    float4 v = ((const float4*)X)[i];
    float o[4] = { v.x, v.y, v.z, v.w };
#pragma unroll
    for (int j = 0; j < 4; j++) {
        int c = c0 + j;
        float t = g[c] * (o[j] - mean[c]) * rsqrtf(var[c] + EPSf) + beta[c];
        if (relu) t = fmaxf(t, 0.f);
        o[j] = t;
    }
    if (Yf) ((float4*)Yf)[i] = make_float4(o[0], o[1], o[2], o[3]);
    bf16 h0 = __float2bfloat16(o[0]), h1 = __float2bfloat16(o[1]);
    bf16 h2 = __float2bfloat16(o[2]), h3 = __float2bfloat16(o[3]);
    __nv_bfloat162* H = (__nv_bfloat162*)Yh;
    __nv_bfloat162* L = (__nv_bfloat162*)Yl;
    H[2*i]   = __nv_bfloat162(h0, h1);
    H[2*i+1] = __nv_bfloat162(h2, h3);
    L[2*i]   = __nv_bfloat162(__float2bfloat16(o[0] - __bfloat162float(h0)),
                              __float2bfloat16(o[1] - __bfloat162float(h1)));
    L[2*i+1] = __nv_bfloat162(__float2bfloat16(o[2] - __bfloat162float(h2)),
                              __float2bfloat16(o[3] - __bfloat162float(h3)));
}

// ---------------- scan ------------------------------------------------------
__global__ void zero_h() {
    int idx = blockIdx.x * blockDim.x + threadIdx.x;
    if (idx < Bb * Dd) {
        g_h[idx] = 0.f;
        g_hh[idx] = __float2bfloat16(0.f);
        g_hl[idx] = __float2bfloat16(0.f);
    }
}

__device__ __forceinline__ float sigmoidf_(float x) { return 1.f / (1.f + expf(-x)); }

__global__ void gru_gate2(const float* __restrict__ actions,
                          const float* __restrict__ je_w,
                          const float* __restrict__ je_b, int t)
{
    int idx = blockIdx.x * blockDim.x + threadIdx.x;
    if (idx >= Bb * Dd) return;
    int b = idx >> 10;
    int d = idx & 1023;
    int row = b * Tt + t;

    const float* a = actions + (size_t)row * Aa;
    float av[8];
#pragma unroll
    for (int j = 0; j < 8; j++) av[j] = a[j];

    const float* G = g_G + (size_t)b * (4 * Dd);

    float hr = G[d]          + g_c[d];
    float hz = G[Dd + d]     + g_c[Dd + d];
    float hn = G[2 * Dd + d] + g_c[2 * Dd + d];
    float hj = G[3 * Dd + d] + je_b[d];
    const float* m2r = g_M2 + (size_t)d * 8;
    const float* m2z = g_M2 + (size_t)(Dd + d) * 8;
    const float* m2n = g_M2 + (size_t)(2 * Dd + d) * 8;
    const float* jea = je_w + (size_t)d * JEW_LD + Dd;
#pragma unroll
    for (int j = 0; j < 8; j++) {
        hr = fmaf(av[j], m2r[j], hr);
        hz = fmaf(av[j], m2z[j], hz);
        hn = fmaf(av[j], m2n[j], hn);
        hj = fmaf(av[j], jea[j], hj);
    }

    const float* gi = g_gi + (size_t)row * (3 * Dd);
    float r = sigmoidf_(gi[d] + hr);
    float z = sigmoidf_(gi[Dd + d] + hz);
    float n = tanhf(gi[2 * Dd + d] + r * hn);
    float xv = g_x[(size_t)row * Dd + d];
    float hnew = (1.f - z) * n + z * hj + xv;
    g_h[idx] = hnew;
    bf16 hh = __float2bfloat16(hnew);
    g_hh[idx] = hh;
    g_hl[idx] = __float2bfloat16(hnew - __bfloat162float(hh));
}

// ---------------- threefry2x32-20 (JAX partitionable) ------------------------
__device__ __forceinline__ uint32_t rotl32_(uint32_t x, int r) {
    return (x << r) | (x >> (32 - r));
}
__device__ __forceinline__ void threefry2x32_(uint32_t k0, uint32_t k1,
                                              uint32_t& x0, uint32_t& x1)
{
    const uint32_t k2 = k0 ^ k1 ^ 0x1BD11BDAu;
    x0 += k0; x1 += k1;
#define TF_R4(a,b,c,d) \
    x0 += x1; x1 = rotl32_(x1, a); x1 ^= x0; \
    x0 += x1; x1 = rotl32_(x1, b); x1 ^= x0; \
    x0 += x1; x1 = rotl32_(x1, c); x1 ^= x0; \
    x0 += x1; x1 = rotl32_(x1, d); x1 ^= x0;
    TF_R4(13,15,26,6)  x0 += k1; x1 += k2 + 1u;
    TF_R4(17,29,16,24) x0 += k2; x1 += k0 + 2u;
    TF_R4(13,15,26,6)  x0 += k0; x1 += k1 + 3u;
    TF_R4(17,29,16,24) x0 += k1; x1 += k2 + 4u;
    TF_R4(13,15,26,6)  x0 += k2; x1 += k0 + 5u;
#undef TF_R4
}

__global__ void gumbel_softmax_k(float* __restrict__ out)
{
    const int bl = blockIdx.x;
    const int d  = threadIdx.x;
    const int i  = bl * ZDn + d;
    const float logit = g_h[i];

    uint32_t c0 = 0u;
    uint32_t c1 = (uint32_t)i;
    threefry2x32_(0u, 42u, c0, c1);
    const uint32_t bits = c0 ^ c1;
    float f = __uint_as_float((bits >> 9) | 0x3f800000u) - 1.0f;
    const float tiny = 1.1754943508222875e-38f;
    float u = fmaxf(f * (1.0f - tiny) + tiny, tiny);
    float gum = -logf(-logf(u));

    float v = logit + gum;

    __shared__ float red[ZDn];
    red[d] = v; __syncthreads();
    for (int s = ZDn / 2; s > 0; s >>= 1) {
        if (d < s) red[d] = fmaxf(red[d], red[d + s]);
        __syncthreads();
    }
    float mx = red[0];
    __syncthreads();
    float e = expf(v - mx);
    red[d] = e; __syncthreads();
    for (int s = ZDn / 2; s > 0; s >>= 1) {
        if (d < s) red[d] += red[d + s];
        __syncthreads();
    }
    float z = e / red[0];

    out[i] = logit;
    out[Bb * ZLn * ZDn + i] = z;
    g_z[i] = z;
    bf16 zh = __float2bfloat16(z);
    g_zh[i] = zh;
    g_zl[i] = __float2bfloat16(z - __bfloat162float(zh));
}

// ---------------- launch ------------------------------------------------------
static inline float* symf(const void* s) {
    void* p = nullptr;
    cudaGetSymbolAddress(&p, s);
    return (float*)p;
}
static inline bf16* symb(const void* s) {
    void* p = nullptr;
    cudaGetSymbolAddress(&p, s);
    return (bf16*)p;
}

extern "C" void kernel_launch(void* const* d_in, const int* in_sizes, int n_in,
                              void* d_out, int out_size)
{
    (void)in_sizes; (void)n_in; (void)out_size;
    const float* obs      = (const float*)d_in[0];
    const float* actions  = (const float*)d_in[1];
    const float* enc_w1   = (const float*)d_in[2];
    const float* enc_b1   = (const float*)d_in[3];
    const float* enc_g1   = (const float*)d_in[4];
    const float* enc_bt1  = (const float*)d_in[5];
    const float* enc_w2   = (const float*)d_in[6];
    const float* enc_b2   = (const float*)d_in[7];
    const float* enc_g2   = (const float*)d_in[8];
    const float* enc_bt2  = (const float*)d_in[9];
    const float* je_w     = (const float*)d_in[10];
    const float* je_b     = (const float*)d_in[11];
    const float* gru_wih  = (const float*)d_in[12];
    const float* gru_bih  = (const float*)d_in[13];
    const float* gru_whh  = (const float*)d_in[14];
    const float* gru_bhh  = (const float*)d_in[15];
    const float* dec_w1   = (const float*)d_in[16];
    const float* dec_b1   = (const float*)d_in[17];
    const float* dec_g1   = (const float*)d_in[18];
    const float* dec_bt1  = (const float*)d_in[19];
    const float* dec_w2   = (const float*)d_in[20];
    const float* dec_b2   = (const float*)d_in[21];
    const float* dec_g2   = (const float*)d_in[22];
    const float* dec_bt2  = (const float*)d_in[23];
    float* out = (float*)d_out;

    float* p_h1 = symf(g_h1);
    float* p_x  = symf(g_x);
    float* p_gi = symf(g_gi);
    float* p_G  = symf(g_G);
    float* p_d1 = symf(g_d1);
    float* p_d2 = symf(g_d2);
    float* p_m  = symf(g_mean);
    float* p_v  = symf(g_var);
    float* p_ws = symf(g_wscan);

    bf16 *p_obsh = symb(g_obsh), *p_obsl = symb(g_obsl);
    bf16 *p_w1h = symb(g_w1h), *p_w1l = symb(g_w1l);
    bf16 *p_h1h = symb(g_h1h), *p_h1l = symb(g_h1l);
    bf16 *p_w2h = symb(g_w2h), *p_w2l = symb(g_w2l);
    bf16 *p_xh = symb(g_xh), *p_xl = symb(g_xl);
    bf16 *p_wihh = symb(g_wihh), *p_wihl = symb(g_wihl);
    bf16 *p_wsh = symb(g_wsh), *p_wsl = symb(g_wsl);
    bf16 *p_hh = symb(g_hh), *p_hl = symb(g_hl);
    bf16 *p_zh = symb(g_zh), *p_zl = symb(g_zl);
    bf16 *p_d1h = symb(g_d1h), *p_d1l = symb(g_d1l);
    bf16 *p_dw1h = symb(g_dw1h), *p_dw1l = symb(g_dw1l);
    bf16 *p_dw2h = symb(g_dw2h), *p_dw2l = symb(g_dw2l);

    cudaFuncSetAttribute(mma_gemm, cudaFuncAttributeMaxDynamicSharedMemorySize, SM2_BYTES);

    dim3 blk(256);
    dim3 statsBlk(32, 8);

    // ---- input/weight conversions ----
    cvt_hl<<<(BT * OBSn / 4 + 255) / 256, blk>>>(obs, p_obsh, p_obsl, BT * OBSn / 4);
    cvt_hl<<<(Hh * OBSn / 4 + 255) / 256, blk>>>(enc_w1, p_w1h, p_w1l, Hh * OBSn / 4);
    cvt_hl<<<(Dd * Hh / 4 + 255) / 256, blk>>>(enc_w2, p_w2h, p_w2l, Dd * Hh / 4);
    cvt_hl<<<(3 * Dd * Dd / 4 + 255) / 256, blk>>>(gru_wih, p_wihh, p_wihl, 3 * Dd * Dd / 4);
    cvt_hl<<<(Hh * Dd / 4 + 255) / 256, blk>>>(dec_w1, p_dw1h, p_dw1l, Hh * Dd / 4);
    cvt_hl<<<(OBSn * Hh / 4 + 255) / 256, blk>>>(dec_w2, p_dw2h, p_dw2l, OBSn * Hh / 4);

    // ---- precompute scan operators ----
    {
        dim3 grid(Dd / 128, 3 * Dd / 128);
        sgemm_ab<<<grid, blk>>>(gru_whh, je_w, p_ws, 3 * Dd, Dd, Dd, Dd, JEW_LD, Dd);
        copy_jew<<<(Dd * Dd + 255) / 256, blk>>>(je_w);
        m2c_k<<<3 * Dd, 128>>>(gru_whh, je_w, je_b, gru_bhh);
        cvt_hl<<<(4 * Dd * Dd / 4 + 255) / 256, blk>>>(p_ws, p_wsh, p_wsl, 4 * Dd * Dd / 4);
    }

    // ---- encoder layer 1 (HMMA) ----
    {
        dim3 grid(Hh / 128, BT / 128);
        mma_gemm<<<grid, blk, SM2_BYTES>>>(p_obsh, p_obsl, p_w1h, p_w1l, enc_b1, p_h1,
                                           BT, Hh, OBSn);
        col_stats<<<Hh / 32, statsBlk>>>(p_h1, BT, Hh, p_m, p_v);
        bn_apply_cvt<<<(BT * Hh / 4 + 255) / 256, blk>>>(p_h1, nullptr, p_h1h, p_h1l,
                                                         p_m, p_v, enc_g1, enc_bt1,
                                                         BT * Hh / 4, Hh, 1);
    }
    // ---- encoder layer 2 (HMMA) ----
    {
        dim3 grid(Dd / 128, BT / 128);
        mma_gemm<<<grid, blk, SM2_BYTES>>>(p_h1h, p_h1l, p_w2h, p_w2l, enc_b2, p_x,
                                           BT, Dd, Hh);
        col_stats<<<Dd / 32, statsBlk>>>(p_x, BT, Dd, p_m, p_v);
        bn_apply_cvt<<<(BT * Dd / 4 + 255) / 256, blk>>>(p_x, p_x, p_xh, p_xl,
                                                         p_m, p_v, enc_g2, enc_bt2,
                                                         BT * Dd / 4, Dd, 0);
    }
    // ---- gi (HMMA) ----
    {
        dim3 grid(3 * Dd / 128, BT / 128);
        mma_gemm<<<grid, blk, SM2_BYTES>>>(p_xh, p_xl, p_wihh, p_wihl, gru_bih, p_gi,
                                           BT, 3 * Dd, Dd);
    }
    // ---- recurrent scan (HMMA GEMM per step) ----
    zero_h<<<(Bb * Dd + 255) / 256, blk>>>();
    {
        dim3 gridS(4 * Dd / 128, Bb / 128);   // (32, 2)
        for (int t = 0; t < Tt; t++) {
            mma_gemm<<<gridS, blk, SM2_BYTES>>>(p_hh, p_hl, p_wsh, p_wsl, nullptr, p_G,
                                                Bb, 4 * Dd, Dd);
            gru_gate2<<<(Bb * Dd + 255) / 256, blk>>>(actions, je_w, je_b, t);
        }
    }
    // ---- gumbel softmax (emits z fp32 + hi/lo) ----
    gumbel_softmax_k<<<Bb * ZLn, ZDn>>>(out);
    // ---- decoder layer 1 (HMMA) ----
    {
        dim3 grid(Hh / 128, Bb / 128);
        mma_gemm<<<grid, blk, SM2_BYTES>>>(p_zh, p_zl, p_dw1h, p_dw1l, dec_b1, p_d1,
                                           Bb, Hh, Dd);
        col_stats<<<Hh / 32, statsBlk>>>(p_d1, Bb, Hh, p_m, p_v);
        bn_apply_cvt<<<(Bb * Hh / 4 + 255) / 256, blk>>>(p_d1, nullptr, p_d1h, p_d1l,
                                                         p_m, p_v, dec_g1, dec_bt1,
                                                         Bb * Hh / 4, Hh, 1);
    }
    // ---- decoder layer 2 (HMMA) -> x_hat ----
    {
        dim3 grid(OBSn / 128, Bb / 128);
        mma_gemm<<<grid, blk, SM2_BYTES>>>(p_d1h, p_d1l, p_dw2h, p_dw2l, dec_b2, p_d2,
                                           Bb, OBSn, Hh);
        col_stats<<<OBSn / 32, statsBlk>>>(p_d2, Bb, OBSn, p_m, p_v);
        int total = Bb * OBSn;
        bn_apply<<<(total + 255) / 256, blk>>>(p_d2, out + 2 * Bb * ZLn * ZDn,
                                               p_m, p_v, dec_g2, dec_bt2, total, OBSn, 0);
    }
}

// round 7
// speedup vs baseline: 3.7433x; 1.0090x over previous
#include <cuda_runtime.h>
#include <cuda_bf16.h>
#include <cstdint>

#define Bb   256
#define Tt   64
#define OBSn 4096
#define Dd   1024
#define Aa   8
#define Hh   2048
#define ZLn  4
#define ZDn  256
#define BT   (Bb*Tt)          // 16384
#define EPSf 1e-5f
#define JEW_LD (Dd + Aa)      // 1032

typedef __nv_bfloat16 bf16;

// ---------------- scratch (static device globals; no allocation) -------------
__device__ float g_h1[BT * Hh];
__device__ float g_x [BT * Dd];
__device__ float g_gi[BT * 3 * Dd];
__device__ float g_h [Bb * Dd];
__device__ float g_z [Bb * ZLn * ZDn];
__device__ float g_d1[Bb * Hh];
__device__ float g_d2[Bb * OBSn];
__device__ float g_mean[4096];
__device__ float g_var [4096];
__device__ float g_wscan[4 * Dd * Dd]; // [4096,1024] rows: 0-3071 whh@jeW, 3072+ jeW
__device__ float g_M2[3 * Dd * Aa];
__device__ float g_c [3 * Dd];

// bf16 hi/lo split buffers
__device__ bf16 g_obsh[BT * OBSn], g_obsl[BT * OBSn];
__device__ bf16 g_w1h [Hh * OBSn], g_w1l [Hh * OBSn];
__device__ bf16 g_h1h [BT * Hh],   g_h1l [BT * Hh];
__device__ bf16 g_w2h [Dd * Hh],   g_w2l [Dd * Hh];
__device__ bf16 g_xh  [BT * Dd],   g_xl  [BT * Dd];
__device__ bf16 g_wihh[3 * Dd * Dd], g_wihl[3 * Dd * Dd];
__device__ bf16 g_wsh [4 * Dd * Dd], g_wsl [4 * Dd * Dd];  // PERMUTED rows 4d+comp
__device__ bf16 g_hh  [Bb * Dd],   g_hl  [Bb * Dd];
__device__ bf16 g_zh  [Bb * Dd],   g_zl  [Bb * Dd];
__device__ bf16 g_d1h [Bb * Hh],   g_d1l [Bb * Hh];
__device__ bf16 g_dw1h[Hh * Dd],   g_dw1l[Hh * Dd];
__device__ bf16 g_dw2h[OBSn * Hh], g_dw2l[OBSn * Hh];

// ======================= PTX helpers =========================================
__device__ __forceinline__ uint32_t smem_u32(const void* p) {
    uint32_t a;
    asm("{ .reg .u64 t; cvta.to.shared.u64 t, %1; cvt.u32.u64 %0, t; }"
        : "=r"(a) : "l"(p));
    return a;
}
__device__ __forceinline__ void cp16(uint32_t s, const void* g) {
    asm volatile("cp.async.cg.shared.global [%0], [%1], 16;" :: "r"(s), "l"(g));
}
__device__ __forceinline__ void cp_commit() {
    asm volatile("cp.async.commit_group;" ::: "memory");
}
__device__ __forceinline__ void cp_wait0() {
    asm volatile("cp.async.wait_group 0;" ::: "memory");
}
__device__ __forceinline__ void cp_wait1() {
    asm volatile("cp.async.wait_group 1;" ::: "memory");
}
__device__ __forceinline__ void cp_wait2() {
    asm volatile("cp.async.wait_group 2;" ::: "memory");
}
__device__ __forceinline__ void ldm_x4(uint32_t* r, uint32_t a) {
    asm volatile("ldmatrix.sync.aligned.m8n8.x4.shared.b16 {%0,%1,%2,%3}, [%4];"
                 : "=r"(r[0]), "=r"(r[1]), "=r"(r[2]), "=r"(r[3]) : "r"(a));
}
__device__ __forceinline__ void ldm_x2(uint32_t* r, uint32_t a) {
    asm volatile("ldmatrix.sync.aligned.m8n8.x2.shared.b16 {%0,%1}, [%2];"
                 : "=r"(r[0]), "=r"(r[1]) : "r"(a));
}
__device__ __forceinline__ void mma_bf16(float* c, const uint32_t* a, const uint32_t* b) {
    asm volatile("mma.sync.aligned.m16n8k16.row.col.f32.bf16.bf16.f32 "
                 "{%0,%1,%2,%3}, {%4,%5,%6,%7}, {%8,%9}, {%0,%1,%2,%3};"
                 : "+f"(c[0]), "+f"(c[1]), "+f"(c[2]), "+f"(c[3])
                 : "r"(a[0]), "r"(a[1]), "r"(a[2]), "r"(a[3]),
                   "r"(b[0]), "r"(b[1]));
}

// =================== HMMA hi/lo GEMM: C = A @ B^T (+bias), 3-stage ===========
// Ah/Al: MxK, Bh/Bl: NxK (bf16, ld=K), C: MxN fp32.
// M%128==0, N%128==0, K%32==0 (NC>=2). Grid (N/128, M/128), 256 threads.
#define LD2   40
#define TILE2 (128 * LD2)
#define STAGE2 (4 * TILE2)
#define SM3_BYTES (3 * STAGE2 * 2)     // 122880

__global__ void __launch_bounds__(256)
mma_gemm(const bf16* __restrict__ Ah, const bf16* __restrict__ Al,
         const bf16* __restrict__ Bh, const bf16* __restrict__ Bl,
         const float* __restrict__ bias, float* __restrict__ C,
         int M, int N, int K)
{
    extern __shared__ bf16 sm2[];

    const int tid = threadIdx.x;
    const int wid = tid >> 5, lane = tid & 31;
    const int wm = wid >> 2, wn = wid & 3;
    const int rowBase = blockIdx.y * 128, colBase = blockIdx.x * 128;
    const int NC = K >> 5;

    float acc[4][4][4];
#pragma unroll
    for (int i = 0; i < 4; i++)
#pragma unroll
        for (int j = 0; j < 4; j++)
#pragma unroll
            for (int k = 0; k < 4; k++) acc[i][j][k] = 0.f;

    const bf16* srcs[4] = { Ah, Al, Bh, Bl };
    const int   rbs [4] = { rowBase, rowBase, colBase, colBase };

    auto load = [&](int c, int st) {
        const int koff = c << 5;
        bf16* stp = sm2 + st * STAGE2;
#pragma unroll
        for (int tI = 0; tI < 4; tI++) {
#pragma unroll
            for (int i = 0; i < 2; i++) {
                int u = tid * 2 + i;
                int row = u >> 2;
                int seg = (u & 3) << 3;
                cp16(smem_u32(stp + tI * TILE2 + row * LD2 + seg),
                     srcs[tI] + (size_t)(rbs[tI] + row) * K + koff + seg);
            }
        }
        cp_commit();
    };

    load(0, 0);
    load(1, 1);
    for (int c = 0; c < NC; c++) {
        const int st = c % 3;
        if (c + 2 < NC) { load(c + 2, (c + 2) % 3); cp_wait2(); }
        else if (c + 1 < NC) cp_wait1();
        else cp_wait0();
        __syncthreads();

        const bf16* stp = sm2 + st * STAGE2;
#pragma unroll
        for (int kh = 0; kh < 2; kh++) {
            const int kcol = kh << 4;
            uint32_t a[2][4][4];
            uint32_t b[2][4][2];
#pragma unroll
            for (int t = 0; t < 2; t++) {
                const bf16* base = stp + t * TILE2;
#pragma unroll
                for (int mt = 0; mt < 4; mt++) {
                    int r = wm * 64 + mt * 16 + (lane & 15);
                    int cc = kcol + ((lane >> 4) << 3);
                    ldm_x4(a[t][mt], smem_u32(base + r * LD2 + cc));
                }
            }
#pragma unroll
            for (int t = 0; t < 2; t++) {
                const bf16* base = stp + (2 + t) * TILE2;
#pragma unroll
                for (int nt = 0; nt < 4; nt++) {
                    int r = wn * 32 + nt * 8 + (lane & 7);
                    int cc = kcol + (((lane >> 3) & 1) << 3);
                    ldm_x2(b[t][nt], smem_u32(base + r * LD2 + cc));
                }
            }
#pragma unroll
            for (int mt = 0; mt < 4; mt++)
#pragma unroll
                for (int nt = 0; nt < 4; nt++) {
                    mma_bf16(acc[mt][nt], a[0][mt], b[0][nt]);
                    mma_bf16(acc[mt][nt], a[0][mt], b[1][nt]);
                    mma_bf16(acc[mt][nt], a[1][mt], b[0][nt]);
                }
        }
        __syncthreads();
    }

#pragma unroll
    for (int mt = 0; mt < 4; mt++) {
        const int row = rowBase + wm * 64 + mt * 16 + (lane >> 2);
#pragma unroll
        for (int nt = 0; nt < 4; nt++) {
            const int col = colBase + wn * 32 + nt * 8 + (lane & 3) * 2;
            float b0 = bias ? bias[col] : 0.f;
            float b1 = bias ? bias[col + 1] : 0.f;
            *(float2*)(C + (size_t)row * N + col) =
                make_float2(acc[mt][nt][0] + b0, acc[mt][nt][1] + b1);
            *(float2*)(C + (size_t)(row + 8) * N + col) =
                make_float2(acc[mt][nt][2] + b0, acc[mt][nt][3] + b1);
        }
    }
}

// =================== fused scan step: GEMM + GRU gate =========================
// A = h (hi/lo) [256,1024]; B = permuted W_scan (hi/lo) [4096,1024].
// Column 4d+comp of G = gh_r/z/n and hj cores for output d.
// Grid (4096/64, 256/128) = (64, 2); 256 threads; 2-stage pipeline.
#define SLD    40
#define SATILE (128 * SLD)
#define SBTILE (64 * SLD)
#define SSTAGE (2 * SATILE + 2 * SBTILE)
#define SSM_BYTES (2 * SSTAGE * 2)     // 61440
#define SLDF   68

__device__ __forceinline__ float sigmoidf_(float x) { return 1.f / (1.f + expf(-x)); }

__global__ void __launch_bounds__(256)
mma_scan(const float* __restrict__ actions,
         const float* __restrict__ je_w,
         const float* __restrict__ je_b, int t)
{
    extern __shared__ bf16 ssm[];

    const int tid = threadIdx.x;
    const int wid = tid >> 5, lane = tid & 31;
    const int wm = wid >> 2, wn = wid & 3;
    const int rowBase = blockIdx.y * 128;
    const int colBase = blockIdx.x * 64;
    const int NC = Dd >> 5;   // 32

    float acc[4][2][4];
#pragma unroll
    for (int i = 0; i < 4; i++)
#pragma unroll
        for (int j = 0; j < 2; j++)
#pragma unroll
            for (int k = 0; k < 4; k++) acc[i][j][k] = 0.f;

    auto load = [&](int c, int st) {
        const int koff = c << 5;
        bf16* stp = ssm + st * SSTAGE;
        // A tiles (128 rows): g_hh, g_hl
#pragma unroll
        for (int tI = 0; tI < 2; tI++) {
            const bf16* src = tI ? g_hl : g_hh;
#pragma unroll
            for (int i = 0; i < 2; i++) {
                int u = tid * 2 + i;
                int row = u >> 2;
                int seg = (u & 3) << 3;
                cp16(smem_u32(stp + tI * SATILE + row * SLD + seg),
                     src + (size_t)(rowBase + row) * Dd + koff + seg);
            }
        }
        // B tiles (64 rows): g_wsh, g_wsl (permuted)
#pragma unroll
        for (int tI = 0; tI < 2; tI++) {
            const bf16* src = tI ? g_wsl : g_wsh;
            int row = tid >> 2;
            int seg = (tid & 3) << 3;
            cp16(smem_u32(stp + 2 * SATILE + tI * SBTILE + row * SLD + seg),
                 src + (size_t)(colBase + row) * Dd + koff + seg);
        }
        cp_commit();
    };

    load(0, 0);
    int st = 0;
    for (int c = 0; c < NC; c++) {
        const bool more = (c + 1) < NC;
        if (more) { load(c + 1, st ^ 1); cp_wait1(); }
        else      { cp_wait0(); }
        __syncthreads();

        const bf16* stp = ssm + st * SSTAGE;
#pragma unroll
        for (int kh = 0; kh < 2; kh++) {
            const int kcol = kh << 4;
            uint32_t a[2][4][4];
            uint32_t b[2][2][2];
#pragma unroll
            for (int tI = 0; tI < 2; tI++) {
                const bf16* base = stp + tI * SATILE;
#pragma unroll
                for (int mt = 0; mt < 4; mt++) {
                    int r = wm * 64 + mt * 16 + (lane & 15);
                    int cc = kcol + ((lane >> 4) << 3);
                    ldm_x4(a[tI][mt], smem_u32(base + r * SLD + cc));
                }
            }
#pragma unroll
            for (int tI = 0; tI < 2; tI++) {
                const bf16* base = stp + 2 * SATILE + tI * SBTILE;
#pragma unroll
                for (int nt = 0; nt < 2; nt++) {
                    int r = wn * 16 + nt * 8 + (lane & 7);
                    int cc = kcol + (((lane >> 3) & 1) << 3);
                    ldm_x2(b[tI][nt], smem_u32(base + r * SLD + cc));
                }
            }
#pragma unroll
            for (int mt = 0; mt < 4; mt++)
#pragma unroll
                for (int nt = 0; nt < 2; nt++) {
                    mma_bf16(acc[mt][nt], a[0][mt], b[0][nt]);
                    mma_bf16(acc[mt][nt], a[0][mt], b[1][nt]);
                    mma_bf16(acc[mt][nt], a[1][mt], b[0][nt]);
                }
        }
        __syncthreads();
        st ^= 1;
    }

    // ---- epilogue: stage tile to smem, compute GRU gate ----
    float* smf = (float*)ssm;    // 128 x SLDF floats = 34816 B <= 61440
#pragma unroll
    for (int mt = 0; mt < 4; mt++) {
        const int row = wm * 64 + mt * 16 + (lane >> 2);
#pragma unroll
        for (int nt = 0; nt < 2; nt++) {
            const int col = wn * 16 + nt * 8 + (lane & 3) * 2;
            smf[row * SLDF + col]     = acc[mt][nt][0];
            smf[row * SLDF + col + 1] = acc[mt][nt][1];
            smf[(row + 8) * SLDF + col]     = acc[mt][nt][2];
            smf[(row + 8) * SLDF + col + 1] = acc[mt][nt][3];
        }
    }
    __syncthreads();

    const int dl = tid & 15;
    const int rg = tid >> 4;             // 0..15 row group
    const int dg = (colBase >> 2) + dl;  // global d

    const float c0 = g_c[dg], c1 = g_c[Dd + dg], c2 = g_c[2 * Dd + dg];
    const float jb = je_b[dg];
    float m2r[8], m2z[8], m2n[8], jea[8];
#pragma unroll
    for (int j = 0; j < 8; j++) {
        m2r[j] = g_M2[(size_t)dg * 8 + j];
        m2z[j] = g_M2[(size_t)(Dd + dg) * 8 + j];
        m2n[j] = g_M2[(size_t)(2 * Dd + dg) * 8 + j];
        jea[j] = je_w[(size_t)dg * JEW_LD + Dd + j];
    }

#pragma unroll
    for (int r8 = 0; r8 < 8; r8++) {
        const int row = rg * 8 + r8;
        const int b = rowBase + row;
        const int trow = b * Tt + t;

        float4 G4 = *(float4*)&smf[row * SLDF + 4 * dl];
        float hr = G4.x + c0;
        float hz = G4.y + c1;
        float hn = G4.z + c2;
        float hj = G4.w + jb;

        const float* a = actions + (size_t)trow * Aa;
#pragma unroll
        for (int j = 0; j < 8; j++) {
            float av = a[j];
            hr = fmaf(av, m2r[j], hr);
            hz = fmaf(av, m2z[j], hz);
            hn = fmaf(av, m2n[j], hn);
            hj = fmaf(av, jea[j], hj);
        }

        const float* gi = g_gi + (size_t)trow * (3 * Dd);
        float r = sigmoidf_(gi[dg] + hr);
        float z = sigmoidf_(gi[Dd + dg] + hz);
        float n = tanhf(gi[2 * Dd + dg] + r * hn);
        float xv = g_x[(size_t)trow * Dd + dg];
        float hnew = (1.f - z) * n + z * hj + xv;

        const int oi = b * Dd + dg;
        g_h[oi] = hnew;
        bf16 hh = __float2bfloat16(hnew);
        g_hh[oi] = hh;
        g_hl[oi] = __float2bfloat16(hnew - __bfloat162float(hh));
    }
}

// =============== hi/lo conversion ============================================
__global__ void cvt_hl(const float* __restrict__ X, bf16* __restrict__ Xh,
                       bf16* __restrict__ Xl, int n4)
{
    int i = blockIdx.x * blockDim.x + threadIdx.x;
    if (i >= n4) return;
    float4 v = ((const float4*)X)[i];
    bf16 h0 = __float2bfloat16(v.x), h1 = __float2bfloat16(v.y);
    bf16 h2 = __float2bfloat16(v.z), h3 = __float2bfloat16(v.w);
    float l0 = v.x - __bfloat162float(h0), l1 = v.y - __bfloat162float(h1);
    float l2 = v.z - __bfloat162float(h2), l3 = v.w - __bfloat162float(h3);
    __nv_bfloat162* H = (__nv_bfloat162*)Xh;
    __nv_bfloat162* L = (__nv_bfloat162*)Xl;
    H[2 * i]     = __nv_bfloat162(h0, h1);
    H[2 * i + 1] = __nv_bfloat162(h2, h3);
    L[2 * i]     = __nv_bfloat162(__float2bfloat16(l0), __float2bfloat16(l1));
    L[2 * i + 1] = __nv_bfloat162(__float2bfloat16(l2), __float2bfloat16(l3));
}

// permuted cvt of W_scan: new row 4d+comp <- old row comp*1024+d (comp<3) / 3072+d
__global__ void cvt_hl_perm_ws()
{
    int i = blockIdx.x * blockDim.x + threadIdx.x;      // over 4M/4
    if (i >= 4 * Dd * Dd / 4) return;
    int flat = i * 4;
    int nrow = flat >> 10;
    int k = flat & 1023;
    int d = nrow >> 2, comp = nrow & 3;
    int orow = (comp < 3) ? comp * Dd + d : 3 * Dd + d;
    float4 v = *(const float4*)&g_wscan[(size_t)orow * Dd + k];
    bf16 h0 = __float2bfloat16(v.x), h1 = __float2bfloat16(v.y);
    bf16 h2 = __float2bfloat16(v.z), h3 = __float2bfloat16(v.w);
    __nv_bfloat162* H = (__nv_bfloat162*)g_wsh;
    __nv_bfloat162* L = (__nv_bfloat162*)g_wsl;
    H[2*i]   = __nv_bfloat162(h0, h1);
    H[2*i+1] = __nv_bfloat162(h2, h3);
    L[2*i]   = __nv_bfloat162(__float2bfloat16(v.x - __bfloat162float(h0)),
                              __float2bfloat16(v.y - __bfloat162float(h1)));
    L[2*i+1] = __nv_bfloat162(__float2bfloat16(v.z - __bfloat162float(h2)),
                              __float2bfloat16(v.w - __bfloat162float(h3)));
}

// =============== SIMT GEMM (precompute only) ==================================
#define BKd 8
__global__ void __launch_bounds__(256)
sgemm_ab(const float* __restrict__ A, const float* __restrict__ Bm,
         float* __restrict__ C, int M, int N, int K, int lda, int ldb, int ldc)
{
    __shared__ float As[BKd][128];
    __shared__ float Bs[BKd][128];
    const int tid = threadIdx.x;
    const int tx = tid & 15, ty = tid >> 4;
    const int rowBase = blockIdx.y * 128, colBase = blockIdx.x * 128;
    const int lrA = tid >> 1, lcA = (tid & 1) * 4;
    const int kkB = tid >> 5, c4B = (tid & 31) * 4;
    const float* Aptr = A + (size_t)(rowBase + lrA) * lda + lcA;
    const float* Bptr = Bm + (size_t)kkB * ldb + colBase + c4B;
    float acc[8][8];
#pragma unroll
    for (int i = 0; i < 8; i++)
#pragma unroll
        for (int j = 0; j < 8; j++) acc[i][j] = 0.f;
    for (int k0 = 0; k0 < K; k0 += BKd) {
        float4 av = *(const float4*)(Aptr + k0);
        float4 bv = *(const float4*)(Bptr + (size_t)k0 * ldb);
        As[lcA+0][lrA]=av.x; As[lcA+1][lrA]=av.y;
        As[lcA+2][lrA]=av.z; As[lcA+3][lrA]=av.w;
        *(float4*)&Bs[kkB][c4B] = bv;
        __syncthreads();
#pragma unroll
        for (int kk = 0; kk < BKd; kk++) {
            float a[8], b[8];
#pragma unroll
            for (int i = 0; i < 8; i++) a[i] = As[kk][ty*8+i];
#pragma unroll
            for (int j = 0; j < 8; j++) b[j] = Bs[kk][tx*8+j];
#pragma unroll
            for (int i = 0; i < 8; i++)
#pragma unroll
                for (int j = 0; j < 8; j++)
                    acc[i][j] = fmaf(a[i], b[j], acc[i][j]);
        }
        __syncthreads();
    }
#pragma unroll
    for (int i = 0; i < 8; i++) {
        const int r = rowBase + ty * 8 + i;
#pragma unroll
        for (int j = 0; j < 8; j++)
            C[(size_t)r * ldc + colBase + tx * 8 + j] = acc[i][j];
    }
}

__global__ void copy_jew(const float* __restrict__ je_w)
{
    int idx = blockIdx.x * blockDim.x + threadIdx.x;
    if (idx >= Dd * Dd) return;
    int j = idx >> 10, k = idx & 1023;
    g_wscan[(size_t)(3 * Dd + j) * Dd + k] = je_w[(size_t)j * JEW_LD + k];
}

__global__ void __launch_bounds__(128)
m2c_k(const float* __restrict__ whh, const float* __restrict__ je_w,
      const float* __restrict__ je_b, const float* __restrict__ bhh)
{
    const int i = blockIdx.x;
    const int t = threadIdx.x;
    float acc[9];
#pragma unroll
    for (int j = 0; j < 9; j++) acc[j] = 0.f;
    for (int k = t; k < Dd; k += 128) {
        float w = whh[(size_t)i * Dd + k];
        const float* jr = je_w + (size_t)k * JEW_LD + Dd;
#pragma unroll
        for (int j = 0; j < 8; j++) acc[j] = fmaf(w, jr[j], acc[j]);
        acc[8] = fmaf(w, je_b[k], acc[8]);
    }
    __shared__ float sh[9][128];
#pragma unroll
    for (int j = 0; j < 9; j++) sh[j][t] = acc[j];
    __syncthreads();
    for (int s = 64; s > 0; s >>= 1) {
        if (t < s)
#pragma unroll
            for (int j = 0; j < 9; j++) sh[j][t] += sh[j][t + s];
        __syncthreads();
    }
    if (t == 0) {
#pragma unroll
        for (int j = 0; j < 8; j++) g_M2[i * 8 + j] = sh[j][0];
        g_c[i] = sh[8][0] + bhh[i];
    }
}

// ---------------- batch stats + BN ------------------------------------------
__global__ void col_stats(const float* __restrict__ X, int M, int N,
                          float* __restrict__ mean, float* __restrict__ var)
{
    const int c = blockIdx.x * 32 + threadIdx.x;
    const int ry = threadIdx.y;
    float s = 0.f, s2 = 0.f;
    for (int r = ry; r < M; r += 8) {
        float v = X[(size_t)r * N + c];
        s += v; s2 += v * v;
    }
    __shared__ float sh[8][32], sh2[8][32];
    sh[ry][threadIdx.x] = s; sh2[ry][threadIdx.x] = s2;
    __syncthreads();
    if (ry == 0) {
#pragma unroll
        for (int y = 1; y < 8; y++) { s += sh[y][threadIdx.x]; s2 += sh2[y][threadIdx.x]; }
        float m = s / (float)M;
        mean[c] = m;
        var[c]  = s2 / (float)M - m * m;
    }
}

__global__ void bn_apply(const float* __restrict__ X, float* __restrict__ Y,
                         const float* __restrict__ mean, const float* __restrict__ var,
                         const float* __restrict__ g, const float* __restrict__ beta,
                         int total, int N, int relu)
{
    int idx = blockIdx.x * blockDim.x + threadIdx.x;
    if (idx >= total) return;
    int c = idx % N;
    float v = g[c] * (X[idx] - mean[c]) * rsqrtf(var[c] + EPSf) + beta[c];
    if (relu) v = fmaxf(v, 0.f);
    Y[idx] = v;
}

__global__ void bn_apply_cvt(const float* __restrict__ X, float* __restrict__ Yf,
                             bf16* __restrict__ Yh, bf16* __restrict__ Yl,
                             const float* __restrict__ mean, const float* __restrict__ var,
                             const float* __restrict__ g, const float* __restrict__ beta,
                             int total4, int N, int relu)
{
    int i = blockIdx.x * blockDim.x + threadIdx.x;
    if (i >= total4) return;
    int c0 = (i * 4) % N;
    float4 v = ((const float4*)X)[i];
    float o[4] = { v.x, v.y, v.z, v.w };
#pragma unroll
    for (int j = 0; j < 4; j++) {
        int c = c0 + j;
        float t = g[c] * (o[j] - mean[c]) * rsqrtf(var[c] + EPSf) + beta[c];
        if (relu) t = fmaxf(t, 0.f);
        o[j] = t;
    }
    if (Yf) ((float4*)Yf)[i] = make_float4(o[0], o[1], o[2], o[3]);
    bf16 h0 = __float2bfloat16(o[0]), h1 = __float2bfloat16(o[1]);
    bf16 h2 = __float2bfloat16(o[2]), h3 = __float2bfloat16(o[3]);
    __nv_bfloat162* H = (__nv_bfloat162*)Yh;
    __nv_bfloat162* L = (__nv_bfloat162*)Yl;
    H[2*i]   = __nv_bfloat162(h0, h1);
    H[2*i+1] = __nv_bfloat162(h2, h3);
    L[2*i]   = __nv_bfloat162(__float2bfloat16(o[0] - __bfloat162float(h0)),
                              __float2bfloat16(o[1] - __bfloat162float(h1)));
    L[2*i+1] = __nv_bfloat162(__float2bfloat16(o[2] - __bfloat162float(h2)),
                              __float2bfloat16(o[3] - __bfloat162float(h3)));
}

// ---------------- misc ------------------------------------------------------
__global__ void zero_h() {
    int idx = blockIdx.x * blockDim.x + threadIdx.x;
    if (idx < Bb * Dd) {
        g_h[idx] = 0.f;
        g_hh[idx] = __float2bfloat16(0.f);
        g_hl[idx] = __float2bfloat16(0.f);
    }
}

// ---------------- threefry2x32-20 (JAX partitionable) ------------------------
__device__ __forceinline__ uint32_t rotl32_(uint32_t x, int r) {
    return (x << r) | (x >> (32 - r));
}
__device__ __forceinline__ void threefry2x32_(uint32_t k0, uint32_t k1,
                                              uint32_t& x0, uint32_t& x1)
{
    const uint32_t k2 = k0 ^ k1 ^ 0x1BD11BDAu;
    x0 += k0; x1 += k1;
#define TF_R4(a,b,c,d) \
    x0 += x1; x1 = rotl32_(x1, a); x1 ^= x0; \
    x0 += x1; x1 = rotl32_(x1, b); x1 ^= x0; \
    x0 += x1; x1 = rotl32_(x1, c); x1 ^= x0; \
    x0 += x1; x1 = rotl32_(x1, d); x1 ^= x0;
    TF_R4(13,15,26,6)  x0 += k1; x1 += k2 + 1u;
    TF_R4(17,29,16,24) x0 += k2; x1 += k0 + 2u;
    TF_R4(13,15,26,6)  x0 += k0; x1 += k1 + 3u;
    TF_R4(17,29,16,24) x0 += k1; x1 += k2 + 4u;
    TF_R4(13,15,26,6)  x0 += k2; x1 += k0 + 5u;
#undef TF_R4
}

__global__ void gumbel_softmax_k(float* __restrict__ out)
{
    const int bl = blockIdx.x;
    const int d  = threadIdx.x;
    const int i  = bl * ZDn + d;
    const float logit = g_h[i];

    uint32_t c0 = 0u;
    uint32_t c1 = (uint32_t)i;
    threefry2x32_(0u, 42u, c0, c1);
    const uint32_t bits = c0 ^ c1;
    float f = __uint_as_float((bits >> 9) | 0x3f800000u) - 1.0f;
    const float tiny = 1.1754943508222875e-38f;
    float u = fmaxf(f * (1.0f - tiny) + tiny, tiny);
    float gum = -logf(-logf(u));

    float v = logit + gum;

    __shared__ float red[ZDn];
    red[d] = v; __syncthreads();
    for (int s = ZDn / 2; s > 0; s >>= 1) {
        if (d < s) red[d] = fmaxf(red[d], red[d + s]);
        __syncthreads();
    }
    float mx = red[0];
    __syncthreads();
    float e = expf(v - mx);
    red[d] = e; __syncthreads();
    for (int s = ZDn / 2; s > 0; s >>= 1) {
        if (d < s) red[d] += red[d + s];
        __syncthreads();
    }
    float z = e / red[0];

    out[i] = logit;
    out[Bb * ZLn * ZDn + i] = z;
    g_z[i] = z;
    bf16 zh = __float2bfloat16(z);
    g_zh[i] = zh;
    g_zl[i] = __float2bfloat16(z - __bfloat162float(zh));
}

// ---------------- launch ------------------------------------------------------
static inline float* symf(const void* s) {
    void* p = nullptr;
    cudaGetSymbolAddress(&p, s);
    return (float*)p;
}
static inline bf16* symb(const void* s) {
    void* p = nullptr;
    cudaGetSymbolAddress(&p, s);
    return (bf16*)p;
}

extern "C" void kernel_launch(void* const* d_in, const int* in_sizes, int n_in,
                              void* d_out, int out_size)
{
    (void)in_sizes; (void)n_in; (void)out_size;
    const float* obs      = (const float*)d_in[0];
    const float* actions  = (const float*)d_in[1];
    const float* enc_w1   = (const float*)d_in[2];
    const float* enc_b1   = (const float*)d_in[3];
    const float* enc_g1   = (const float*)d_in[4];
    const float* enc_bt1  = (const float*)d_in[5];
    const float* enc_w2   = (const float*)d_in[6];
    const float* enc_b2   = (const float*)d_in[7];
    const float* enc_g2   = (const float*)d_in[8];
    const float* enc_bt2  = (const float*)d_in[9];
    const float* je_w     = (const float*)d_in[10];
    const float* je_b     = (const float*)d_in[11];
    const float* gru_wih  = (const float*)d_in[12];
    const float* gru_bih  = (const float*)d_in[13];
    const float* gru_whh  = (const float*)d_in[14];
    const float* gru_bhh  = (const float*)d_in[15];
    const float* dec_w1   = (const float*)d_in[16];
    const float* dec_b1   = (const float*)d_in[17];
    const float* dec_g1   = (const float*)d_in[18];
    const float* dec_bt1  = (const float*)d_in[19];
    const float* dec_w2   = (const float*)d_in[20];
    const float* dec_b2   = (const float*)d_in[21];
    const float* dec_g2   = (const float*)d_in[22];
    const float* dec_bt2  = (const float*)d_in[23];
    float* out = (float*)d_out;

    float* p_h1 = symf(g_h1);
    float* p_x  = symf(g_x);
    float* p_gi = symf(g_gi);
    float* p_d1 = symf(g_d1);
    float* p_d2 = symf(g_d2);
    float* p_m  = symf(g_mean);
    float* p_v  = symf(g_var);
    float* p_ws = symf(g_wscan);

    bf16 *p_obsh = symb(g_obsh), *p_obsl = symb(g_obsl);
    bf16 *p_w1h = symb(g_w1h), *p_w1l = symb(g_w1l);
    bf16 *p_h1h = symb(g_h1h), *p_h1l = symb(g_h1l);
    bf16 *p_w2h = symb(g_w2h), *p_w2l = symb(g_w2l);
    bf16 *p_xh = symb(g_xh), *p_xl = symb(g_xl);
    bf16 *p_wihh = symb(g_wihh), *p_wihl = symb(g_wihl);
    bf16 *p_zh = symb(g_zh), *p_zl = symb(g_zl);
    bf16 *p_d1h = symb(g_d1h), *p_d1l = symb(g_d1l);
    bf16 *p_dw1h = symb(g_dw1h), *p_dw1l = symb(g_dw1l);
    bf16 *p_dw2h = symb(g_dw2h), *p_dw2l = symb(g_dw2l);

    cudaFuncSetAttribute(mma_gemm, cudaFuncAttributeMaxDynamicSharedMemorySize, SM3_BYTES);
    cudaFuncSetAttribute(mma_scan, cudaFuncAttributeMaxDynamicSharedMemorySize, SSM_BYTES);

    dim3 blk(256);
    dim3 statsBlk(32, 8);

    // ---- input/weight conversions ----
    cvt_hl<<<(BT * OBSn / 4 + 255) / 256, blk>>>(obs, p_obsh, p_obsl, BT * OBSn / 4);
    cvt_hl<<<(Hh * OBSn / 4 + 255) / 256, blk>>>(enc_w1, p_w1h, p_w1l, Hh * OBSn / 4);
    cvt_hl<<<(Dd * Hh / 4 + 255) / 256, blk>>>(enc_w2, p_w2h, p_w2l, Dd * Hh / 4);
    cvt_hl<<<(3 * Dd * Dd / 4 + 255) / 256, blk>>>(gru_wih, p_wihh, p_wihl, 3 * Dd * Dd / 4);
    cvt_hl<<<(Hh * Dd / 4 + 255) / 256, blk>>>(dec_w1, p_dw1h, p_dw1l, Hh * Dd / 4);
    cvt_hl<<<(OBSn * Hh / 4 + 255) / 256, blk>>>(dec_w2, p_dw2h, p_dw2l, OBSn * Hh / 4);

    // ---- precompute scan operators ----
    {
        dim3 grid(Dd / 128, 3 * Dd / 128);
        sgemm_ab<<<grid, blk>>>(gru_whh, je_w, p_ws, 3 * Dd, Dd, Dd, Dd, JEW_LD, Dd);
        copy_jew<<<(Dd * Dd + 255) / 256, blk>>>(je_w);
        m2c_k<<<3 * Dd, 128>>>(gru_whh, je_w, je_b, gru_bhh);
        cvt_hl_perm_ws<<<(4 * Dd * Dd / 4 + 255) / 256, blk>>>();
    }

    // ---- encoder layer 1 (HMMA) ----
    {
        dim3 grid(Hh / 128, BT / 128);
        mma_gemm<<<grid, blk, SM3_BYTES>>>(p_obsh, p_obsl, p_w1h, p_w1l, enc_b1, p_h1,
                                           BT, Hh, OBSn);
        col_stats<<<Hh / 32, statsBlk>>>(p_h1, BT, Hh, p_m, p_v);
        bn_apply_cvt<<<(BT * Hh / 4 + 255) / 256, blk>>>(p_h1, nullptr, p_h1h, p_h1l,
                                                         p_m, p_v, enc_g1, enc_bt1,
                                                         BT * Hh / 4, Hh, 1);
    }
    // ---- encoder layer 2 (HMMA) ----
    {
        dim3 grid(Dd / 128, BT / 128);
        mma_gemm<<<grid, blk, SM3_BYTES>>>(p_h1h, p_h1l, p_w2h, p_w2l, enc_b2, p_x,
                                           BT, Dd, Hh);
        col_stats<<<Dd / 32, statsBlk>>>(p_x, BT, Dd, p_m, p_v);
        bn_apply_cvt<<<(BT * Dd / 4 + 255) / 256, blk>>>(p_x, p_x, p_xh, p_xl,
                                                         p_m, p_v, enc_g2, enc_bt2,
                                                         BT * Dd / 4, Dd, 0);
    }
    // ---- gi (HMMA) ----
    {
        dim3 grid(3 * Dd / 128, BT / 128);
        mma_gemm<<<grid, blk, SM3_BYTES>>>(p_xh, p_xl, p_wihh, p_wihl, gru_bih, p_gi,
                                           BT, 3 * Dd, Dd);
    }
    // ---- recurrent scan: ONE fused kernel per step ----
    zero_h<<<(Bb * Dd + 255) / 256, blk>>>();
    {
        dim3 gridS(4 * Dd / 64, Bb / 128);   // (64, 2) = 128 CTAs
        for (int t = 0; t < Tt; t++)
            mma_scan<<<gridS, blk, SSM_BYTES>>>(actions, je_w, je_b, t);
    }
    // ---- gumbel softmax ----
    gumbel_softmax_k<<<Bb * ZLn, ZDn>>>(out);
    // ---- decoder layer 1 (HMMA) ----
    {
        dim3 grid(Hh / 128, Bb / 128);
        mma_gemm<<<grid, blk, SM3_BYTES>>>(p_zh, p_zl, p_dw1h, p_dw1l, dec_b1, p_d1,
                                           Bb, Hh, Dd);
        col_stats<<<Hh / 32, statsBlk>>>(p_d1, Bb, Hh, p_m, p_v);
        bn_apply_cvt<<<(Bb * Hh / 4 + 255) / 256, blk>>>(p_d1, nullptr, p_d1h, p_d1l,
                                                         p_m, p_v, dec_g1, dec_bt1,
                                                         Bb * Hh / 4, Hh, 1);
    }
    // ---- decoder layer 2 (HMMA) -> x_hat ----
    {
        dim3 grid(OBSn / 128, Bb / 128);
        mma_gemm<<<grid, blk, SM3_BYTES>>>(p_d1h, p_d1l, p_dw2h, p_dw2l, dec_b2, p_d2,
                                           Bb, OBSn, Hh);
        col_stats<<<OBSn / 32, statsBlk>>>(p_d2, Bb, OBSn, p_m, p_v);
        int total = Bb * OBSn;
        bn_apply<<<(total + 255) / 256, blk>>>(p_d2, out + 2 * Bb * ZLn * ZDn,
                                               p_m, p_v, dec_g2, dec_bt2, total, OBSn, 0);
    }
}